// round 1
// baseline (speedup 1.0000x reference)
#include <cuda_runtime.h>
#include <math.h>

#define BSZ 2
#define SEQ 2048
#define NX 768
#define NH 12
#define HD 64
#define MROWS (BSZ*SEQ)      // 4096
#define NQKV (3*NX)          // 2304

// Scratch (no cudaMalloc allowed): contiguous Q/K/V in the reference's
// direct-reshape layout, plus attention output pre-projection.
__device__ float g_Q[BSZ*SEQ*NX];
__device__ float g_K[BSZ*SEQ*NX];
__device__ float g_V[BSZ*SEQ*NX];
__device__ float g_A[BSZ*SEQ*NX];

#define FMA16(ACC, AV, BV)                                                   \
    ACC[0][0] += AV.x*BV.x; ACC[0][1] += AV.x*BV.y;                          \
    ACC[0][2] += AV.x*BV.z; ACC[0][3] += AV.x*BV.w;                          \
    ACC[1][0] += AV.y*BV.x; ACC[1][1] += AV.y*BV.y;                          \
    ACC[1][2] += AV.y*BV.z; ACC[1][3] += AV.y*BV.w;                          \
    ACC[2][0] += AV.z*BV.x; ACC[2][1] += AV.z*BV.y;                          \
    ACC[2][2] += AV.z*BV.z; ACC[2][3] += AV.z*BV.w;                          \
    ACC[3][0] += AV.w*BV.x; ACC[3][1] += AV.w*BV.y;                          \
    ACC[3][2] += AV.w*BV.z; ACC[3][3] += AV.w*BV.w;

__device__ __forceinline__ float redmax16(float v) {
    v = fmaxf(v, __shfl_xor_sync(0xffffffffu, v, 1));
    v = fmaxf(v, __shfl_xor_sync(0xffffffffu, v, 2));
    v = fmaxf(v, __shfl_xor_sync(0xffffffffu, v, 4));
    v = fmaxf(v, __shfl_xor_sync(0xffffffffu, v, 8));
    return v;
}
__device__ __forceinline__ float redsum16(float v) {
    v += __shfl_xor_sync(0xffffffffu, v, 1);
    v += __shfl_xor_sync(0xffffffffu, v, 2);
    v += __shfl_xor_sync(0xffffffffu, v, 4);
    v += __shfl_xor_sync(0xffffffffu, v, 8);
    return v;
}

// ---------------------------------------------------------------------------
// GEMM: C = A @ B + bias.  A:[M,K] rm, B:[K,N] rm.
// MODE 1: A = param, epilogue scatters QKV into g_Q/g_K/g_V.
// MODE 0: A = g_A (device global), epilogue writes C.
// BM=BN=64, BK=16, 256 threads, 4x4 microtile.
// ---------------------------------------------------------------------------
template<int MODE>
__global__ void __launch_bounds__(256)
gemm_bias_kernel(const float* __restrict__ A, const float* __restrict__ B,
                 const float* __restrict__ bias, float* __restrict__ C,
                 int M, int N, int K)
{
    __shared__ float As[16][64];   // As[k][m] (A transposed in smem)
    __shared__ float Bs[16][64];   // Bs[k][n]

    const int tid = threadIdx.x;
    const int tx = tid & 15;       // 0..15  (n groups of 4)
    const int ty = tid >> 4;       // 0..15  (m groups of 4)
    const int m0 = blockIdx.y * 64;
    const int n0 = blockIdx.x * 64;

    const int arow = tid >> 2;          // 0..63
    const int acol = (tid & 3) << 2;    // 0,4,8,12
    const int brow = tid >> 4;          // 0..15
    const int bcol = (tid & 15) << 2;   // 0..60

    const float* Ap = (MODE == 0) ? (const float*)g_A : A;

    float acc[4][4];
#pragma unroll
    for (int i = 0; i < 4; i++)
#pragma unroll
        for (int j = 0; j < 4; j++) acc[i][j] = 0.0f;

    for (int k0 = 0; k0 < K; k0 += 16) {
        float4 av = *(const float4*)(Ap + (size_t)(m0 + arow) * K + k0 + acol);
        float4 bv = *(const float4*)(B  + (size_t)(k0 + brow) * N + n0 + bcol);
        __syncthreads();
        As[acol + 0][arow] = av.x;
        As[acol + 1][arow] = av.y;
        As[acol + 2][arow] = av.z;
        As[acol + 3][arow] = av.w;
        *(float4*)&Bs[brow][bcol] = bv;
        __syncthreads();
#pragma unroll
        for (int kk = 0; kk < 16; kk++) {
            float4 a = *(const float4*)&As[kk][ty << 2];
            float4 b = *(const float4*)&Bs[kk][tx << 2];
            FMA16(acc, a, b);
        }
    }

#pragma unroll
    for (int i = 0; i < 4; i++) {
        const int m = m0 + (ty << 2) + i;
#pragma unroll
        for (int j = 0; j < 4; j++) {
            const int n = n0 + (tx << 2) + j;
            const float v = acc[i][j] + bias[n];
            if (MODE == 0) {
                C[(size_t)m * N + n] = v;
            } else {
                const int b = m >> 11;          // m / SEQ
                const int s = m & (SEQ - 1);    // m % SEQ
                const size_t off = (size_t)b * SEQ * NX + (size_t)s * NX;
                if (n < NX)            g_Q[off + n] = v;
                else if (n < 2 * NX)   g_K[off + n - NX] = v;
                else                   g_V[off + n - 2 * NX] = v;
            }
        }
    }
}

// ---------------------------------------------------------------------------
// Causal attention, flash-style. One CTA per (q-block of 64, head, batch).
// Per-head Q/K/V are contiguous [SEQ, HD] matrices (reference's direct
// reshape): base = b*SEQ*NX + h*SEQ*HD.
// S and P@V computed as 64x64x64 register-tiled GEMMs (4x4 per thread).
// smem: Qs (Q^T), KPs (K^T, reused as P^T), Vs  -> exactly 48 KB.
// ---------------------------------------------------------------------------
__global__ void __launch_bounds__(256)
attn_kernel(const float* __restrict__ amask)
{
    __shared__ float Qs[64][64];   // Qs[d][r]
    __shared__ float KPs[64][64];  // phase 1: K^T  KPs[d][kcol]; phase 2: P^T KPs[kcol][r]
    __shared__ float Vs[64][64];   // Vs[kcol][d]

    const int tid = threadIdx.x;
    const int tx = tid & 15;       // col group
    const int ty = tid >> 4;       // row group
    const int qb = blockIdx.x;
    const int h  = blockIdx.y;
    const int b  = blockIdx.z;
    const int q0 = qb * 64;

    const size_t headoff = (size_t)b * SEQ * NX + (size_t)h * SEQ * HD;
    const float* Qg = g_Q + headoff;
    const float* Kg = g_K + headoff;
    const float* Vg = g_V + headoff;
    const float* am = amask + (size_t)b * SEQ;

    const int lrow_id = tid >> 2;          // 0..63 (loader row)
    const int lcol    = (tid & 3) << 4;    // 0,16,32,48 (loader col base)

    // Load Q tile transposed: Qs[d][r] = Q[(q0+r)*HD + d]
#pragma unroll
    for (int t = 0; t < 4; t++) {
        float4 v = *(const float4*)(Qg + (size_t)(q0 + lrow_id) * HD + lcol + t * 4);
        Qs[lcol + t*4 + 0][lrow_id] = v.x;
        Qs[lcol + t*4 + 1][lrow_id] = v.y;
        Qs[lcol + t*4 + 2][lrow_id] = v.z;
        Qs[lcol + t*4 + 3][lrow_id] = v.w;
    }

    float acc[4][4];
    float mrow[4], lrow[4];
#pragma unroll
    for (int i = 0; i < 4; i++) {
        mrow[i] = -3.0e38f;
        lrow[i] = 0.0f;
#pragma unroll
        for (int j = 0; j < 4; j++) acc[i][j] = 0.0f;
    }

    const float scale = 0.125f;   // 1/sqrt(64)
    const int nkb = qb + 1;       // causal: only blocks with k0 <= q_max

    for (int kb = 0; kb < nkb; kb++) {
        const int k0 = kb * 64;
        __syncthreads();
        // Load K transposed, V natural
#pragma unroll
        for (int t = 0; t < 4; t++) {
            float4 kv = *(const float4*)(Kg + (size_t)(k0 + lrow_id) * HD + lcol + t * 4);
            KPs[lcol + t*4 + 0][lrow_id] = kv.x;
            KPs[lcol + t*4 + 1][lrow_id] = kv.y;
            KPs[lcol + t*4 + 2][lrow_id] = kv.z;
            KPs[lcol + t*4 + 3][lrow_id] = kv.w;
            float4 vv = *(const float4*)(Vg + (size_t)(k0 + lrow_id) * HD + lcol + t * 4);
            *(float4*)&Vs[lrow_id][lcol + t * 4] = vv;
        }
        __syncthreads();

        // S = Q @ K^T, 4x4 per thread: rows q0+ty*4+i, cols k0+tx*4+j
        float s[4][4];
#pragma unroll
        for (int i = 0; i < 4; i++)
#pragma unroll
            for (int j = 0; j < 4; j++) s[i][j] = 0.0f;
#pragma unroll
        for (int d = 0; d < 64; d++) {
            float4 a  = *(const float4*)&Qs[d][ty << 2];
            float4 bq = *(const float4*)&KPs[d][tx << 2];
            FMA16(s, a, bq);
        }

        // Mask + online softmax (row state duplicated across the 16-lane tx group)
#pragma unroll
        for (int i = 0; i < 4; i++) {
            const int q = q0 + (ty << 2) + i;
            float rmax = -3.0e38f;
#pragma unroll
            for (int j = 0; j < 4; j++) {
                const int k = k0 + (tx << 2) + j;
                const float amv = am[k];
                const float sv = (k <= q) ? (s[i][j] * scale + amv)
                                          : (-10000.0f + amv);
                s[i][j] = sv;
                rmax = fmaxf(rmax, sv);
            }
            rmax = redmax16(rmax);
            const float mnew = fmaxf(mrow[i], rmax);
            const float corr = __expf(mrow[i] - mnew);
            float rsum = 0.0f;
#pragma unroll
            for (int j = 0; j < 4; j++) {
                const float p = __expf(s[i][j] - mnew);
                s[i][j] = p;
                rsum += p;
            }
            rsum = redsum16(rsum);
            lrow[i] = lrow[i] * corr + rsum;
            mrow[i] = mnew;
#pragma unroll
            for (int j = 0; j < 4; j++) acc[i][j] *= corr;
        }

        // Write P^T into the K buffer (done reading K this iteration)
        __syncthreads();
#pragma unroll
        for (int i = 0; i < 4; i++)
#pragma unroll
            for (int j = 0; j < 4; j++)
                KPs[(tx << 2) + j][(ty << 2) + i] = s[i][j];
        __syncthreads();

        // O += P @ V: rows q (ty), cols d (tx)
#pragma unroll
        for (int kk = 0; kk < 64; kk++) {
            float4 p  = *(const float4*)&KPs[kk][ty << 2];
            float4 vv = *(const float4*)&Vs[kk][tx << 2];
            FMA16(acc, p, vv);
        }
    }

    // Epilogue: normalize, write to g_A[b, q, h*64 + d] (the transpose(0,2,1,3))
#pragma unroll
    for (int i = 0; i < 4; i++) {
        const int q = q0 + (ty << 2) + i;
        const float inv = 1.0f / lrow[i];
#pragma unroll
        for (int j = 0; j < 4; j++) {
            const int d = (tx << 2) + j;
            g_A[(size_t)b * SEQ * NX + (size_t)q * NX + h * HD + d] = acc[i][j] * inv;
        }
    }
}

// ---------------------------------------------------------------------------
extern "C" void kernel_launch(void* const* d_in, const int* in_sizes, int n_in,
                              void* d_out, int out_size)
{
    const float* hidden = (const float*)d_in[0];  // [bs, seq, 768]
    const float* amask  = (const float*)d_in[1];  // [bs, 1, 1, seq]
    const float* w_attn = (const float*)d_in[2];  // [768, 2304]
    const float* b_attn = (const float*)d_in[3];  // [2304]
    const float* w_proj = (const float*)d_in[4];  // [768, 768]
    const float* b_proj = (const float*)d_in[5];  // [768]
    float* out = (float*)d_out;                   // [bs, seq, 768]

    // 1) QKV = X @ W_attn + b, scattered into contiguous per-head Q/K/V
    dim3 g1(NQKV / 64, MROWS / 64);
    gemm_bias_kernel<1><<<g1, 256>>>(hidden, w_attn, b_attn, nullptr,
                                     MROWS, NQKV, NX);

    // 2) Causal multi-head attention
    dim3 g2(SEQ / 64, NH, BSZ);
    attn_kernel<<<g2, 256>>>(amask);

    // 3) out = A @ W_proj + b
    dim3 g3(NX / 64, MROWS / 64);
    gemm_bias_kernel<0><<<g3, 256>>>(nullptr, w_proj, b_proj, out,
                                     MROWS, NX, NX);
}

// round 3
// speedup vs baseline: 1.1732x; 1.1732x over previous
#include <cuda_runtime.h>
#include <math.h>

#define BSZ 2
#define SEQ 2048
#define NX 768
#define NH 12
#define HD 64
#define MROWS (BSZ*SEQ)      // 4096
#define NQKV (3*NX)          // 2304

// Scratch (no cudaMalloc allowed)
__device__ float g_Q[BSZ*SEQ*NX];
__device__ float g_K[BSZ*SEQ*NX];
__device__ float g_V[BSZ*SEQ*NX];
__device__ float g_A[BSZ*SEQ*NX];

__device__ __forceinline__ float redmax16(float v) {
    v = fmaxf(v, __shfl_xor_sync(0xffffffffu, v, 1));
    v = fmaxf(v, __shfl_xor_sync(0xffffffffu, v, 2));
    v = fmaxf(v, __shfl_xor_sync(0xffffffffu, v, 4));
    v = fmaxf(v, __shfl_xor_sync(0xffffffffu, v, 8));
    return v;
}
__device__ __forceinline__ float redsum16(float v) {
    v += __shfl_xor_sync(0xffffffffu, v, 1);
    v += __shfl_xor_sync(0xffffffffu, v, 2);
    v += __shfl_xor_sync(0xffffffffu, v, 4);
    v += __shfl_xor_sync(0xffffffffu, v, 8);
    return v;
}

// ---------------------------------------------------------------------------
// GEMM: C = A @ B + bias.  A:[M,K] rm, B:[K,N] rm.
// 128x128 tile, BK=8, 256 threads, 8x8 microtile, double-buffered smem.
// MODE 1: A = param (hidden), epilogue scatters QKV into g_Q/g_K/g_V.
// MODE 0: A = g_A, epilogue writes C directly.
// ---------------------------------------------------------------------------
template<int MODE>
__global__ void __launch_bounds__(256, 2)
gemm128(const float* __restrict__ A, const float* __restrict__ B,
        const float* __restrict__ bias, float* __restrict__ C,
        int M, int N, int K)
{
    __shared__ float As[2][8][132];   // A^T: As[buf][k][m], padded stride
    __shared__ float Bs[2][8][128];   // Bs[buf][k][n]

    const int tid = threadIdx.x;
    const int tx = tid & 15;          // n micro-col group (8 wide)
    const int ty = tid >> 4;          // m micro-row group (8 wide)
    const int m0 = blockIdx.y * 128;
    const int n0 = blockIdx.x * 128;

    const int arow = tid >> 1;        // 0..127
    const int acol = (tid & 1) << 2;  // 0 or 4
    const int brow = tid >> 5;        // 0..7
    const int bcol = (tid & 31) << 2; // 0..124

    const float* Ap = (MODE == 0) ? (const float*)g_A : A;
    const float* Aptr = Ap + (size_t)(m0 + arow) * K + acol;
    const float* Bptr = B  + (size_t)brow * N + n0 + bcol;

    float acc[8][8];
#pragma unroll
    for (int i = 0; i < 8; i++)
#pragma unroll
        for (int j = 0; j < 8; j++) acc[i][j] = 0.0f;

    const int nsteps = K >> 3;   // K/8

    // prologue: load step 0 and commit to buf 0
    float4 av = *(const float4*)Aptr;
    float4 bv = *(const float4*)Bptr;
    As[0][acol + 0][arow] = av.x;
    As[0][acol + 1][arow] = av.y;
    As[0][acol + 2][arow] = av.z;
    As[0][acol + 3][arow] = av.w;
    *(float4*)&Bs[0][brow][bcol] = bv;
    __syncthreads();

    for (int s = 0; s < nsteps; s++) {
        const int buf = s & 1;
        if (s + 1 < nsteps) {
            av = *(const float4*)(Aptr + (s + 1) * 8);
            bv = *(const float4*)(Bptr + (size_t)(s + 1) * 8 * N);
        }
#pragma unroll
        for (int kk = 0; kk < 8; kk++) {
            float4 a0 = *(const float4*)&As[buf][kk][ty << 3];
            float4 a1 = *(const float4*)&As[buf][kk][(ty << 3) + 4];
            float4 b0 = *(const float4*)&Bs[buf][kk][tx << 3];
            float4 b1 = *(const float4*)&Bs[buf][kk][(tx << 3) + 4];
            float ar[8] = {a0.x, a0.y, a0.z, a0.w, a1.x, a1.y, a1.z, a1.w};
            float br[8] = {b0.x, b0.y, b0.z, b0.w, b1.x, b1.y, b1.z, b1.w};
#pragma unroll
            for (int i = 0; i < 8; i++)
#pragma unroll
                for (int j = 0; j < 8; j++) acc[i][j] += ar[i] * br[j];
        }
        if (s + 1 < nsteps) {
            const int nb = buf ^ 1;
            As[nb][acol + 0][arow] = av.x;
            As[nb][acol + 1][arow] = av.y;
            As[nb][acol + 2][arow] = av.z;
            As[nb][acol + 3][arow] = av.w;
            *(float4*)&Bs[nb][brow][bcol] = bv;
        }
        __syncthreads();
    }

    // bias for this thread's 8 columns
    float4 bi0 = *(const float4*)(bias + n0 + (tx << 3));
    float4 bi1 = *(const float4*)(bias + n0 + (tx << 3) + 4);
    const float bb[8] = {bi0.x, bi0.y, bi0.z, bi0.w, bi1.x, bi1.y, bi1.z, bi1.w};

#pragma unroll
    for (int i = 0; i < 8; i++) {
        const int m = m0 + (ty << 3) + i;
        float4 w0, w1;
        w0.x = acc[i][0] + bb[0]; w0.y = acc[i][1] + bb[1];
        w0.z = acc[i][2] + bb[2]; w0.w = acc[i][3] + bb[3];
        w1.x = acc[i][4] + bb[4]; w1.y = acc[i][5] + bb[5];
        w1.z = acc[i][6] + bb[6]; w1.w = acc[i][7] + bb[7];
        const int n = n0 + (tx << 3);
        if (MODE == 0) {
            *(float4*)(C + (size_t)m * N + n) = w0;
            *(float4*)(C + (size_t)m * N + n + 4) = w1;
        } else {
            // 128-wide n-tiles never straddle the 768 boundaries
            const int sect = n0 / NX;              // 0=Q, 1=K, 2=V
            const int nn = n - sect * NX;
            const int b = m >> 11;
            const int sq = m & (SEQ - 1);
            float* dst = (sect == 0) ? g_Q : (sect == 1) ? g_K : g_V;
            float* p = dst + (size_t)b * SEQ * NX + (size_t)sq * NX + nn;
            *(float4*)p = w0;
            *(float4*)(p + 4) = w1;
        }
    }
}

// ---------------------------------------------------------------------------
// Causal attention, flash-style. q-tile 128, k-tile 64, 256 threads,
// 8x4 microtile. Per-head Q/K/V contiguous [SEQ, HD] (reference's direct
// reshape). Dynamic smem: Q^T[64][132] + K^T[64][68] + V[64][68] + P^T[64][132]
// = 100 KB -> 2 CTAs/SM.
// ---------------------------------------------------------------------------
#define QS 132
#define KS 68
#define ATTN_SMEM_FLOATS (64*QS + 64*KS + 64*KS + 64*QS)

__global__ void __launch_bounds__(256, 2)
attn128(const float* __restrict__ amask)
{
    extern __shared__ float sm[];
    float (*Qs)[QS] = (float(*)[QS])sm;
    float (*Ks)[KS] = (float(*)[KS])(sm + 64 * QS);
    float (*Vs)[KS] = (float(*)[KS])(sm + 64 * QS + 64 * KS);
    float (*Ps)[QS] = (float(*)[QS])(sm + 64 * QS + 2 * 64 * KS);

    const int tid = threadIdx.x;
    const int tx = tid & 15;      // k cols (4 wide)
    const int ty = tid >> 4;      // q rows (8 wide)
    const int qb = gridDim.x - 1 - blockIdx.x;  // long CTAs first
    const int h  = blockIdx.y;
    const int b  = blockIdx.z;
    const int q0 = qb * 128;

    const size_t headoff = (size_t)b * SEQ * NX + (size_t)h * SEQ * HD;
    const float* Qg = g_Q + headoff;
    const float* Kg = g_K + headoff;
    const float* Vg = g_V + headoff;
    const float* am = amask + (size_t)b * SEQ;

    // Load Q transposed: Qs[d][r]
    {
        const int r = tid >> 1;
        const int cb = (tid & 1) << 5;   // 0 or 32
#pragma unroll
        for (int t = 0; t < 8; t++) {
            float4 v = *(const float4*)(Qg + (size_t)(q0 + r) * HD + cb + t * 4);
            Qs[cb + t*4 + 0][r] = v.x;
            Qs[cb + t*4 + 1][r] = v.y;
            Qs[cb + t*4 + 2][r] = v.z;
            Qs[cb + t*4 + 3][r] = v.w;
        }
    }

    float acc[8][4];
    float mrow[8], lrow[8];
#pragma unroll
    for (int i = 0; i < 8; i++) {
        mrow[i] = -3.0e38f; lrow[i] = 0.0f;
#pragma unroll
        for (int j = 0; j < 4; j++) acc[i][j] = 0.0f;
    }

    // K^T loader: per-warp rows are consecutive -> conflict-free scatter store
    const int krow = tid & 63;
    const int kcb  = (tid >> 6) << 4;   // 0,16,32,48
    // V loader: natural layout, coalesced
    const int vrow = tid >> 2;
    const int vcb  = (tid & 3) << 4;

    const int nkb = 2 * qb + 2;

    for (int kb = 0; kb < nkb; kb++) {
        const int k0 = kb * 64;
        __syncthreads();   // Ks/Vs free (prev S & PV done), Ps free
#pragma unroll
        for (int t = 0; t < 4; t++) {
            float4 kv = *(const float4*)(Kg + (size_t)(k0 + krow) * HD + kcb + t * 4);
            Ks[kcb + t*4 + 0][krow] = kv.x;
            Ks[kcb + t*4 + 1][krow] = kv.y;
            Ks[kcb + t*4 + 2][krow] = kv.z;
            Ks[kcb + t*4 + 3][krow] = kv.w;
            float4 vv = *(const float4*)(Vg + (size_t)(k0 + vrow) * HD + vcb + t * 4);
            *(float4*)&Vs[vrow][vcb + t * 4] = vv;
        }
        __syncthreads();

        // S = Q @ K^T : 8x4 per thread over d=0..63
        float s[8][4];
#pragma unroll
        for (int i = 0; i < 8; i++)
#pragma unroll
            for (int j = 0; j < 4; j++) s[i][j] = 0.0f;
#pragma unroll
        for (int d = 0; d < 64; d++) {
            float4 a0 = *(const float4*)&Qs[d][ty << 3];
            float4 a1 = *(const float4*)&Qs[d][(ty << 3) + 4];
            float4 bq = *(const float4*)&Ks[d][tx << 2];
            float ar[8] = {a0.x, a0.y, a0.z, a0.w, a1.x, a1.y, a1.z, a1.w};
#pragma unroll
            for (int i = 0; i < 8; i++) {
                s[i][0] += ar[i] * bq.x;
                s[i][1] += ar[i] * bq.y;
                s[i][2] += ar[i] * bq.z;
                s[i][3] += ar[i] * bq.w;
            }
        }

        // mask + online softmax
#pragma unroll
        for (int i = 0; i < 8; i++) {
            const int q = q0 + (ty << 3) + i;
            float rmax = -3.0e38f;
#pragma unroll
            for (int j = 0; j < 4; j++) {
                const int k = k0 + (tx << 2) + j;
                const float amv = am[k];
                const float sv = (k <= q) ? (s[i][j] * 0.125f + amv)
                                          : (-10000.0f + amv);
                s[i][j] = sv;
                rmax = fmaxf(rmax, sv);
            }
            rmax = redmax16(rmax);
            const float mnew = fmaxf(mrow[i], rmax);
            const float corr = __expf(mrow[i] - mnew);
            float rsum = 0.0f;
#pragma unroll
            for (int j = 0; j < 4; j++) {
                const float p = __expf(s[i][j] - mnew);
                s[i][j] = p;
                rsum += p;
            }
            rsum = redsum16(rsum);
            lrow[i] = lrow[i] * corr + rsum;
            mrow[i] = mnew;
#pragma unroll
            for (int j = 0; j < 4; j++) acc[i][j] *= corr;
        }

        // store P^T with register transpose (float4 along q)
#pragma unroll
        for (int j = 0; j < 4; j++) {
            float4 p0 = make_float4(s[0][j], s[1][j], s[2][j], s[3][j]);
            float4 p1 = make_float4(s[4][j], s[5][j], s[6][j], s[7][j]);
            *(float4*)&Ps[(tx << 2) + j][ty << 3] = p0;
            *(float4*)&Ps[(tx << 2) + j][(ty << 3) + 4] = p1;
        }
        __syncthreads();

        // O += P @ V
#pragma unroll
        for (int kk = 0; kk < 64; kk++) {
            float4 p0 = *(const float4*)&Ps[kk][ty << 3];
            float4 p1 = *(const float4*)&Ps[kk][(ty << 3) + 4];
            float4 vv = *(const float4*)&Vs[kk][tx << 2];
            float pr[8] = {p0.x, p0.y, p0.z, p0.w, p1.x, p1.y, p1.z, p1.w};
#pragma unroll
            for (int i = 0; i < 8; i++) {
                acc[i][0] += pr[i] * vv.x;
                acc[i][1] += pr[i] * vv.y;
                acc[i][2] += pr[i] * vv.z;
                acc[i][3] += pr[i] * vv.w;
            }
        }
    }

    // epilogue: normalize + write g_A[b, q, h*64 + d]
#pragma unroll
    for (int i = 0; i < 8; i++) {
        const int q = q0 + (ty << 3) + i;
        const float inv = 1.0f / lrow[i];
        float4 o = make_float4(acc[i][0] * inv, acc[i][1] * inv,
                               acc[i][2] * inv, acc[i][3] * inv);
        *(float4*)&g_A[(size_t)b * SEQ * NX + (size_t)q * NX + h * HD + (tx << 2)] = o;
    }
}

// ---------------------------------------------------------------------------
extern "C" void kernel_launch(void* const* d_in, const int* in_sizes, int n_in,
                              void* d_out, int out_size)
{
    const float* hidden = (const float*)d_in[0];
    const float* amask  = (const float*)d_in[1];
    const float* w_attn = (const float*)d_in[2];
    const float* b_attn = (const float*)d_in[3];
    const float* w_proj = (const float*)d_in[4];
    const float* b_proj = (const float*)d_in[5];
    float* out = (float*)d_out;

    // Unconditional (no static guard — harness rule). Idempotent host-side
    // attribute set; not a stream op, so graph-capture-safe.
    cudaFuncSetAttribute(attn128, cudaFuncAttributeMaxDynamicSharedMemorySize,
                         ATTN_SMEM_FLOATS * (int)sizeof(float));

    // 1) QKV = X @ W_attn + b, scattered into contiguous per-head Q/K/V
    dim3 g1(NQKV / 128, MROWS / 128);
    gemm128<1><<<g1, 256>>>(hidden, w_attn, b_attn, nullptr, MROWS, NQKV, NX);

    // 2) Causal multi-head attention
    dim3 g2(SEQ / 128, NH, BSZ);
    attn128<<<g2, 256, ATTN_SMEM_FLOATS * (int)sizeof(float)>>>(amask);

    // 3) out = A @ W_proj + b
    dim3 g3(NX / 128, MROWS / 128);
    gemm128<0><<<g3, 256>>>(nullptr, w_proj, b_proj, out, MROWS, NX, NX);
}

// round 6
// speedup vs baseline: 1.5417x; 1.3141x over previous
#include <cuda_runtime.h>
#include <cuda_bf16.h>
#include <math.h>
#include <stdint.h>

#define BSZ 2
#define SEQ 2048
#define NX 768
#define NH 12
#define HD 64
#define MROWS (BSZ*SEQ)      // 4096
#define NQKV (3*NX)          // 2304

// Scratch (no cudaMalloc allowed)
__device__ float g_Q[BSZ*SEQ*NX];
__device__ float g_K[BSZ*SEQ*NX];
__device__ float g_V[BSZ*SEQ*NX];
__device__ __nv_bfloat16 g_Ah[BSZ*SEQ*NX];   // activation hi (bf16)
__device__ __nv_bfloat16 g_Al[BSZ*SEQ*NX];   // activation lo (bf16)
__device__ __nv_bfloat16 g_Bh1[NQKV*NX];     // w_attn^T hi  [2304][768]
__device__ __nv_bfloat16 g_Bl1[NQKV*NX];
__device__ __nv_bfloat16 g_Bh2[NX*NX];       // w_proj^T hi  [768][768]
__device__ __nv_bfloat16 g_Bl2[NX*NX];

// ---------------------------------------------------------------------------
// helpers
// ---------------------------------------------------------------------------
__device__ __forceinline__ uint32_t smem_u32(const void* p) {
    uint32_t a;
    asm("{ .reg .u64 t; cvta.to.shared.u64 t, %1; cvt.u32.u64 %0, t; }"
        : "=r"(a) : "l"(p));
    return a;
}
// mma.sync bf16 (baseline PTX, legal on plain sm_103 target)
__device__ __forceinline__ void mma_bf16(float* d, const uint32_t* a, const uint32_t* b) {
    asm volatile(
        "mma.sync.aligned.m16n8k16.row.col.f32.bf16.bf16.f32 "
        "{%0,%1,%2,%3}, {%4,%5,%6,%7}, {%8,%9}, {%0,%1,%2,%3};"
        : "+f"(d[0]), "+f"(d[1]), "+f"(d[2]), "+f"(d[3])
        : "r"(a[0]), "r"(a[1]), "r"(a[2]), "r"(a[3]), "r"(b[0]), "r"(b[1]));
}
__device__ __forceinline__ void ldm_x4(uint32_t* r, uint32_t addr) {
    asm volatile("ldmatrix.sync.aligned.m8n8.x4.shared.b16 {%0,%1,%2,%3}, [%4];"
                 : "=r"(r[0]), "=r"(r[1]), "=r"(r[2]), "=r"(r[3]) : "r"(addr));
}
__device__ __forceinline__ void ldm_x2(uint32_t* r, uint32_t addr) {
    asm volatile("ldmatrix.sync.aligned.m8n8.x2.shared.b16 {%0,%1}, [%2];"
                 : "=r"(r[0]), "=r"(r[1]) : "r"(addr));
}
__device__ __forceinline__ float redmax16(float v) {
    v = fmaxf(v, __shfl_xor_sync(0xffffffffu, v, 1));
    v = fmaxf(v, __shfl_xor_sync(0xffffffffu, v, 2));
    v = fmaxf(v, __shfl_xor_sync(0xffffffffu, v, 4));
    v = fmaxf(v, __shfl_xor_sync(0xffffffffu, v, 8));
    return v;
}
__device__ __forceinline__ float redsum16(float v) {
    v += __shfl_xor_sync(0xffffffffu, v, 1);
    v += __shfl_xor_sync(0xffffffffu, v, 2);
    v += __shfl_xor_sync(0xffffffffu, v, 4);
    v += __shfl_xor_sync(0xffffffffu, v, 8);
    return v;
}

// ---------------------------------------------------------------------------
// Pre-pass 1: transpose + bf16-split weights.  B[K,N] fp32 -> Th/Tl [N][K] bf16
// ---------------------------------------------------------------------------
__global__ void __launch_bounds__(256)
wsplitT(const float* __restrict__ B, __nv_bfloat16* __restrict__ Th,
        __nv_bfloat16* __restrict__ Tl, int K, int N)
{
    __shared__ float t[32][33];
    const int c  = threadIdx.x & 31;
    const int r4 = threadIdx.x >> 5;     // 0..7
    const int n0 = blockIdx.x * 32;
    const int k0 = blockIdx.y * 32;
#pragma unroll
    for (int i = 0; i < 4; i++)
        t[r4 + 8*i][c] = B[(size_t)(k0 + r4 + 8*i) * N + n0 + c];
    __syncthreads();
#pragma unroll
    for (int i = 0; i < 4; i++) {
        const int n = n0 + r4 + 8*i;
        const float v = t[c][r4 + 8*i];
        const __nv_bfloat16 hi = __float2bfloat16_rn(v);
        Th[(size_t)n * K + k0 + c] = hi;
        Tl[(size_t)n * K + k0 + c] = __float2bfloat16_rn(v - __bfloat162float(hi));
    }
}

// Pre-pass 2: elementwise bf16 split of activations
__global__ void __launch_bounds__(256)
asplit(const float* __restrict__ X, __nv_bfloat16* __restrict__ H,
       __nv_bfloat16* __restrict__ L)
{
    const size_t i = (size_t)blockIdx.x * 256 + threadIdx.x;
    float4 x = ((const float4*)X)[i];
    __nv_bfloat16 h0 = __float2bfloat16_rn(x.x);
    __nv_bfloat16 h1 = __float2bfloat16_rn(x.y);
    __nv_bfloat16 h2 = __float2bfloat16_rn(x.z);
    __nv_bfloat16 h3 = __float2bfloat16_rn(x.w);
    __nv_bfloat162* H2 = (__nv_bfloat162*)H;
    __nv_bfloat162* L2 = (__nv_bfloat162*)L;
    H2[2*i]   = __nv_bfloat162(h0, h1);
    H2[2*i+1] = __nv_bfloat162(h2, h3);
    L2[2*i]   = __nv_bfloat162(__float2bfloat16_rn(x.x - __bfloat162float(h0)),
                               __float2bfloat16_rn(x.y - __bfloat162float(h1)));
    L2[2*i+1] = __nv_bfloat162(__float2bfloat16_rn(x.z - __bfloat162float(h2)),
                               __float2bfloat16_rn(x.w - __bfloat162float(h3)));
}

// ---------------------------------------------------------------------------
// HMMA bf16 3-product GEMM: C = A @ Bt^T + bias
// A hi/lo bf16 [M][K]; Bt hi/lo bf16 [N][K].
// CTA 128x128, 8 warps (2x4), warp tile 64x32, K-chunk 16, double buffered.
// Smem rows padded to 24 bf16 (48 B): ldmatrix chunk banks all distinct.
// MODE 1: scatter into g_Q/g_K/g_V.  MODE 0: write C.
// ---------------------------------------------------------------------------
#define RP 24                       // padded row length in bf16 (48 bytes)
__global__ void __launch_bounds__(256)
mma_gemm_impl(const __nv_bfloat16* __restrict__ Ahg, const __nv_bfloat16* __restrict__ Alg,
              const __nv_bfloat16* __restrict__ Bhg, const __nv_bfloat16* __restrict__ Blg,
              const float* __restrict__ bias, float* __restrict__ C,
              int N, int K, int MODE)
{
    __shared__ __nv_bfloat16 sAh[2][128*RP];
    __shared__ __nv_bfloat16 sAl[2][128*RP];
    __shared__ __nv_bfloat16 sBh[2][128*RP];
    __shared__ __nv_bfloat16 sBl[2][128*RP];

    const int tid  = threadIdx.x;
    const int wid  = tid >> 5;
    const int lane = tid & 31;
    const int wm   = wid >> 2;        // 0..1 -> 64 rows
    const int wn   = wid & 3;         // 0..3 -> 32 cols
    const int m0 = blockIdx.y * 128;
    const int n0 = blockIdx.x * 128;

    // loader: each thread handles one row (0..127), 8-bf16 half (16 B)
    const int row  = tid >> 1;
    const int half = tid & 1;
    const __nv_bfloat16* pAh = Ahg + (size_t)(m0 + row) * K + half * 8;
    const __nv_bfloat16* pAl = Alg + (size_t)(m0 + row) * K + half * 8;
    const __nv_bfloat16* pBh = Bhg + (size_t)(n0 + row) * K + half * 8;
    const __nv_bfloat16* pBl = Blg + (size_t)(n0 + row) * K + half * 8;
    const int sdst = row * RP + half * 8;   // bf16 elems (16B-aligned bytes)

    // ldmatrix lane base addresses (byte offsets within one buffer)
    const uint32_t bAh = smem_u32(sAh), bAl = smem_u32(sAl);
    const uint32_t bBh = smem_u32(sBh), bBl = smem_u32(sBl);
    uint32_t a_off[4], b_off[4];
    {
        const int ar = lane & 15, ak = (lane >> 4) * 16;      // bytes
        const int bn = lane & 7,  bk = ((lane >> 3) & 1) * 16;
#pragma unroll
        for (int i = 0; i < 4; i++) a_off[i] = (uint32_t)((wm*64 + i*16 + ar) * (RP*2) + ak);
#pragma unroll
        for (int j = 0; j < 4; j++) b_off[j] = (uint32_t)((wn*32 + j*8 + bn) * (RP*2) + bk);
    }

    float acc[4][4][4];
#pragma unroll
    for (int i = 0; i < 4; i++)
#pragma unroll
        for (int j = 0; j < 4; j++)
#pragma unroll
            for (int t = 0; t < 4; t++) acc[i][j][t] = 0.0f;

    const int NC = K >> 4;   // 48 for K=768

    // prologue
    uint4 vah = *(const uint4*)pAh;
    uint4 val = *(const uint4*)pAl;
    uint4 vbh = *(const uint4*)pBh;
    uint4 vbl = *(const uint4*)pBl;
    *(uint4*)&sAh[0][sdst] = vah;
    *(uint4*)&sAl[0][sdst] = val;
    *(uint4*)&sBh[0][sdst] = vbh;
    *(uint4*)&sBl[0][sdst] = vbl;
    __syncthreads();

    for (int kc = 0; kc < NC; kc++) {
        const int buf = kc & 1;
        const uint32_t bo = (uint32_t)buf * (128*RP*2);
        if (kc + 1 < NC) {
            const int ko = (kc + 1) * 16;
            vah = *(const uint4*)(pAh + ko);
            val = *(const uint4*)(pAl + ko);
            vbh = *(const uint4*)(pBh + ko);
            vbl = *(const uint4*)(pBl + ko);
        }

        uint32_t fbh[4][2], fbl[4][2];
#pragma unroll
        for (int j = 0; j < 4; j++) {
            ldm_x2(fbh[j], bBh + bo + b_off[j]);
            ldm_x2(fbl[j], bBl + bo + b_off[j]);
        }
#pragma unroll
        for (int i = 0; i < 4; i++) {
            uint32_t fah[4], fal[4];
            ldm_x4(fah, bAh + bo + a_off[i]);
            ldm_x4(fal, bAl + bo + a_off[i]);
#pragma unroll
            for (int j = 0; j < 4; j++) {
                mma_bf16(acc[i][j], fah, fbh[j]);
                mma_bf16(acc[i][j], fah, fbl[j]);
                mma_bf16(acc[i][j], fal, fbh[j]);
            }
        }

        if (kc + 1 < NC) {
            const int so = buf ^ 1;
            *(uint4*)&sAh[so][sdst] = vah;
            *(uint4*)&sAl[so][sdst] = val;
            *(uint4*)&sBh[so][sdst] = vbh;
            *(uint4*)&sBl[so][sdst] = vbl;
        }
        __syncthreads();
    }

    // epilogue: C frag rows lane/4 (+8), cols 2*(lane%4)+{0,1}
    const int lr = lane >> 2;
    const int lc = (lane & 3) << 1;
#pragma unroll
    for (int i = 0; i < 4; i++) {
        const int m = m0 + wm*64 + i*16 + lr;
#pragma unroll
        for (int j = 0; j < 4; j++) {
            const int n = n0 + wn*32 + j*8 + lc;
            const float b0 = bias[n], b1 = bias[n + 1];
            float2 v0 = make_float2(acc[i][j][0] + b0, acc[i][j][1] + b1);
            float2 v1 = make_float2(acc[i][j][2] + b0, acc[i][j][3] + b1);
            if (MODE == 0) {
                *(float2*)(C + (size_t)m * N + n) = v0;
                *(float2*)(C + (size_t)(m + 8) * N + n) = v1;
            } else {
                const int sect = n0 / NX;            // 0=Q,1=K,2=V
                const int nn = n - sect * NX;
                float* dst = (sect == 0) ? g_Q : (sect == 1) ? g_K : g_V;
                const int b  = m >> 11;
                const int sq = m & (SEQ - 1);
                float* p = dst + (size_t)b * SEQ * NX + (size_t)sq * NX + nn;
                *(float2*)p = v0;
                const int m8 = m + 8;
                const int b8  = m8 >> 11;
                const int sq8 = m8 & (SEQ - 1);
                float* p8 = dst + (size_t)b8 * SEQ * NX + (size_t)sq8 * NX + nn;
                *(float2*)p8 = v1;
            }
        }
    }
}

// ---------------------------------------------------------------------------
// Causal attention (FFMA, identical math to the passing R3 kernel);
// epilogue emits bf16 hi/lo into g_Ah/g_Al (feeds the proj GEMM).
// ---------------------------------------------------------------------------
#define QS 132
#define KS 68
#define ATTN_SMEM_FLOATS (64*QS + 64*KS + 64*KS + 64*QS)

__global__ void __launch_bounds__(256, 2)
attn128(const float* __restrict__ amask)
{
    extern __shared__ float sm[];
    float (*Qs)[QS] = (float(*)[QS])sm;
    float (*Ks)[KS] = (float(*)[KS])(sm + 64 * QS);
    float (*Vs)[KS] = (float(*)[KS])(sm + 64 * QS + 64 * KS);
    float (*Ps)[QS] = (float(*)[QS])(sm + 64 * QS + 2 * 64 * KS);

    const int tid = threadIdx.x;
    const int tx = tid & 15;
    const int ty = tid >> 4;
    const int qb = gridDim.x - 1 - blockIdx.x;
    const int h  = blockIdx.y;
    const int b  = blockIdx.z;
    const int q0 = qb * 128;

    const size_t headoff = (size_t)b * SEQ * NX + (size_t)h * SEQ * HD;
    const float* Qg = g_Q + headoff;
    const float* Kg = g_K + headoff;
    const float* Vg = g_V + headoff;
    const float* am = amask + (size_t)b * SEQ;

    {
        const int r = tid >> 1;
        const int cb = (tid & 1) << 5;
#pragma unroll
        for (int t = 0; t < 8; t++) {
            float4 v = *(const float4*)(Qg + (size_t)(q0 + r) * HD + cb + t * 4);
            Qs[cb + t*4 + 0][r] = v.x;
            Qs[cb + t*4 + 1][r] = v.y;
            Qs[cb + t*4 + 2][r] = v.z;
            Qs[cb + t*4 + 3][r] = v.w;
        }
    }

    float acc[8][4];
    float mrow[8], lrow[8];
#pragma unroll
    for (int i = 0; i < 8; i++) {
        mrow[i] = -3.0e38f; lrow[i] = 0.0f;
#pragma unroll
        for (int j = 0; j < 4; j++) acc[i][j] = 0.0f;
    }

    const int krow = tid & 63;
    const int kcb  = (tid >> 6) << 4;
    const int vrow = tid >> 2;
    const int vcb  = (tid & 3) << 4;

    const int nkb = 2 * qb + 2;

    for (int kb = 0; kb < nkb; kb++) {
        const int k0 = kb * 64;
        __syncthreads();
#pragma unroll
        for (int t = 0; t < 4; t++) {
            float4 kv = *(const float4*)(Kg + (size_t)(k0 + krow) * HD + kcb + t * 4);
            Ks[kcb + t*4 + 0][krow] = kv.x;
            Ks[kcb + t*4 + 1][krow] = kv.y;
            Ks[kcb + t*4 + 2][krow] = kv.z;
            Ks[kcb + t*4 + 3][krow] = kv.w;
            float4 vv = *(const float4*)(Vg + (size_t)(k0 + vrow) * HD + vcb + t * 4);
            *(float4*)&Vs[vrow][vcb + t * 4] = vv;
        }
        __syncthreads();

        float s[8][4];
#pragma unroll
        for (int i = 0; i < 8; i++)
#pragma unroll
            for (int j = 0; j < 4; j++) s[i][j] = 0.0f;
#pragma unroll
        for (int d = 0; d < 64; d++) {
            float4 a0 = *(const float4*)&Qs[d][ty << 3];
            float4 a1 = *(const float4*)&Qs[d][(ty << 3) + 4];
            float4 bq = *(const float4*)&Ks[d][tx << 2];
            float ar[8] = {a0.x, a0.y, a0.z, a0.w, a1.x, a1.y, a1.z, a1.w};
#pragma unroll
            for (int i = 0; i < 8; i++) {
                s[i][0] += ar[i] * bq.x;
                s[i][1] += ar[i] * bq.y;
                s[i][2] += ar[i] * bq.z;
                s[i][3] += ar[i] * bq.w;
            }
        }

#pragma unroll
        for (int i = 0; i < 8; i++) {
            const int q = q0 + (ty << 3) + i;
            float rmax = -3.0e38f;
#pragma unroll
            for (int j = 0; j < 4; j++) {
                const int k = k0 + (tx << 2) + j;
                const float amv = am[k];
                const float sv = (k <= q) ? (s[i][j] * 0.125f + amv)
                                          : (-10000.0f + amv);
                s[i][j] = sv;
                rmax = fmaxf(rmax, sv);
            }
            rmax = redmax16(rmax);
            const float mnew = fmaxf(mrow[i], rmax);
            const float corr = __expf(mrow[i] - mnew);
            float rsum = 0.0f;
#pragma unroll
            for (int j = 0; j < 4; j++) {
                const float p = __expf(s[i][j] - mnew);
                s[i][j] = p;
                rsum += p;
            }
            rsum = redsum16(rsum);
            lrow[i] = lrow[i] * corr + rsum;
            mrow[i] = mnew;
#pragma unroll
            for (int j = 0; j < 4; j++) acc[i][j] *= corr;
        }

        __syncthreads();
#pragma unroll
        for (int j = 0; j < 4; j++) {
            float4 p0 = make_float4(s[0][j], s[1][j], s[2][j], s[3][j]);
            float4 p1 = make_float4(s[4][j], s[5][j], s[6][j], s[7][j]);
            *(float4*)&Ps[(tx << 2) + j][ty << 3] = p0;
            *(float4*)&Ps[(tx << 2) + j][(ty << 3) + 4] = p1;
        }
        __syncthreads();

#pragma unroll
        for (int kk = 0; kk < 64; kk++) {
            float4 p0 = *(const float4*)&Ps[kk][ty << 3];
            float4 p1 = *(const float4*)&Ps[kk][(ty << 3) + 4];
            float4 vv = *(const float4*)&Vs[kk][tx << 2];
            float pr[8] = {p0.x, p0.y, p0.z, p0.w, p1.x, p1.y, p1.z, p1.w};
#pragma unroll
            for (int i = 0; i < 8; i++) {
                acc[i][0] += pr[i] * vv.x;
                acc[i][1] += pr[i] * vv.y;
                acc[i][2] += pr[i] * vv.z;
                acc[i][3] += pr[i] * vv.w;
            }
        }
    }

    // epilogue: normalize + bf16 hi/lo split into g_Ah/g_Al
#pragma unroll
    for (int i = 0; i < 8; i++) {
        const int q = q0 + (ty << 3) + i;
        const float inv = 1.0f / lrow[i];
        float o[4] = {acc[i][0] * inv, acc[i][1] * inv,
                      acc[i][2] * inv, acc[i][3] * inv};
        __nv_bfloat16 hi[4], lo[4];
#pragma unroll
        for (int t = 0; t < 4; t++) {
            hi[t] = __float2bfloat16_rn(o[t]);
            lo[t] = __float2bfloat16_rn(o[t] - __bfloat162float(hi[t]));
        }
        const size_t idx = (size_t)b * SEQ * NX + (size_t)q * NX + h * HD + (tx << 2);
        __nv_bfloat162* H2 = (__nv_bfloat162*)&g_Ah[idx];
        __nv_bfloat162* L2 = (__nv_bfloat162*)&g_Al[idx];
        H2[0] = __nv_bfloat162(hi[0], hi[1]);
        H2[1] = __nv_bfloat162(hi[2], hi[3]);
        L2[0] = __nv_bfloat162(lo[0], lo[1]);
        L2[1] = __nv_bfloat162(lo[2], lo[3]);
    }
}

// ---------------------------------------------------------------------------
extern "C" void kernel_launch(void* const* d_in, const int* in_sizes, int n_in,
                              void* d_out, int out_size)
{
    const float* hidden = (const float*)d_in[0];
    const float* amask  = (const float*)d_in[1];
    const float* w_attn = (const float*)d_in[2];
    const float* b_attn = (const float*)d_in[3];
    const float* w_proj = (const float*)d_in[4];
    const float* b_proj = (const float*)d_in[5];
    float* out = (float*)d_out;

    // Host-side attribute set: not a stream op, graph-capture-safe, idempotent.
    cudaFuncSetAttribute(attn128, cudaFuncAttributeMaxDynamicSharedMemorySize,
                         ATTN_SMEM_FLOATS * (int)sizeof(float));

    __nv_bfloat16 *Bh1, *Bl1, *Bh2, *Bl2, *Ah, *Al;
    cudaGetSymbolAddress((void**)&Bh1, g_Bh1);
    cudaGetSymbolAddress((void**)&Bl1, g_Bl1);
    cudaGetSymbolAddress((void**)&Bh2, g_Bh2);
    cudaGetSymbolAddress((void**)&Bl2, g_Bl2);
    cudaGetSymbolAddress((void**)&Ah,  g_Ah);
    cudaGetSymbolAddress((void**)&Al,  g_Al);

    // Pre-pass: transpose+split weights (fp32 -> bf16 hi/lo), split activations
    wsplitT<<<dim3(NQKV/32, NX/32), 256>>>(w_attn, Bh1, Bl1, NX, NQKV);
    wsplitT<<<dim3(NX/32,   NX/32), 256>>>(w_proj, Bh2, Bl2, NX, NX);
    asplit<<<(MROWS*NX)/(256*4), 256>>>(hidden, Ah, Al);

    // 1) QKV = X @ W_attn + b  (HMMA bf16 3-product), scatter into Q/K/V
    mma_gemm_impl<<<dim3(NQKV/128, MROWS/128), 256>>>(
        Ah, Al, Bh1, Bl1, b_attn, nullptr, NQKV, NX, 1);

    // 2) Causal attention (FFMA); writes bf16 hi/lo activations
    attn128<<<dim3(SEQ/128, NH, BSZ), 256, ATTN_SMEM_FLOATS * (int)sizeof(float)>>>(amask);

    // 3) out = A @ W_proj + b  (HMMA bf16 3-product)
    mma_gemm_impl<<<dim3(NX/128, MROWS/128), 256>>>(
        Ah, Al, Bh2, Bl2, b_proj, out, NX, NX, 0);
}

// round 9
// speedup vs baseline: 2.4925x; 1.6168x over previous
#include <cuda_runtime.h>
#include <cuda_bf16.h>
#include <math.h>
#include <stdint.h>

#define BSZ 2
#define SEQ 2048
#define NX 768
#define NH 12
#define HD 64
#define MROWS (BSZ*SEQ)      // 4096
#define NQKV (3*NX)          // 2304

// Scratch (no cudaMalloc allowed)
__device__ __nv_bfloat16 g_Qh[BSZ*NH*SEQ*HD];
__device__ __nv_bfloat16 g_Ql[BSZ*NH*SEQ*HD];
__device__ __nv_bfloat16 g_Kh[BSZ*NH*SEQ*HD];
__device__ __nv_bfloat16 g_Kl[BSZ*NH*SEQ*HD];
__device__ __nv_bfloat16 g_Vh[BSZ*NH*SEQ*HD];
__device__ __nv_bfloat16 g_Vl[BSZ*NH*SEQ*HD];
__device__ __nv_bfloat16 g_Ah[BSZ*SEQ*NX];   // attn out hi (feeds proj)
__device__ __nv_bfloat16 g_Al[BSZ*SEQ*NX];   // attn out lo
__device__ __nv_bfloat16 g_Bh1[NQKV*NX];     // w_attn^T hi  [2304][768]
__device__ __nv_bfloat16 g_Bl1[NQKV*NX];
__device__ __nv_bfloat16 g_Bh2[NX*NX];       // w_proj^T hi  [768][768]
__device__ __nv_bfloat16 g_Bl2[NX*NX];

// ---------------------------------------------------------------------------
// helpers
// ---------------------------------------------------------------------------
__device__ __forceinline__ uint32_t smem_u32(const void* p) {
    uint32_t a;
    asm("{ .reg .u64 t; cvta.to.shared.u64 t, %1; cvt.u32.u64 %0, t; }"
        : "=r"(a) : "l"(p));
    return a;
}
__device__ __forceinline__ void mma_bf16(float* d, const uint32_t* a, const uint32_t* b) {
    asm volatile(
        "mma.sync.aligned.m16n8k16.row.col.f32.bf16.bf16.f32 "
        "{%0,%1,%2,%3}, {%4,%5,%6,%7}, {%8,%9}, {%0,%1,%2,%3};"
        : "+f"(d[0]), "+f"(d[1]), "+f"(d[2]), "+f"(d[3])
        : "r"(a[0]), "r"(a[1]), "r"(a[2]), "r"(a[3]), "r"(b[0]), "r"(b[1]));
}
__device__ __forceinline__ void ldm_x4(uint32_t* r, uint32_t addr) {
    asm volatile("ldmatrix.sync.aligned.m8n8.x4.shared.b16 {%0,%1,%2,%3}, [%4];"
                 : "=r"(r[0]), "=r"(r[1]), "=r"(r[2]), "=r"(r[3]) : "r"(addr));
}
__device__ __forceinline__ void ldm_x2(uint32_t* r, uint32_t addr) {
    asm volatile("ldmatrix.sync.aligned.m8n8.x2.shared.b16 {%0,%1}, [%2];"
                 : "=r"(r[0]), "=r"(r[1]) : "r"(addr));
}
__device__ __forceinline__ void ldm_x2t(uint32_t* r, uint32_t addr) {
    asm volatile("ldmatrix.sync.aligned.m8n8.x2.trans.shared.b16 {%0,%1}, [%2];"
                 : "=r"(r[0]), "=r"(r[1]) : "r"(addr));
}
// split two fp32 into packed bf16 hi2 / lo2
__device__ __forceinline__ void split2(float a, float b, uint32_t& hi, uint32_t& lo) {
    __nv_bfloat16 ha = __float2bfloat16_rn(a), hb = __float2bfloat16_rn(b);
    __nv_bfloat16 la = __float2bfloat16_rn(a - __bfloat162float(ha));
    __nv_bfloat16 lb = __float2bfloat16_rn(b - __bfloat162float(hb));
    __nv_bfloat162 H(ha, hb), L(la, lb);
    hi = *(uint32_t*)&H; lo = *(uint32_t*)&L;
}

// ---------------------------------------------------------------------------
// Pre-pass 1: transpose + bf16-split weights.  B[K,N] fp32 -> Th/Tl [N][K]
// ---------------------------------------------------------------------------
__global__ void __launch_bounds__(256)
wsplitT(const float* __restrict__ B, __nv_bfloat16* __restrict__ Th,
        __nv_bfloat16* __restrict__ Tl, int K, int N)
{
    __shared__ float t[32][33];
    const int c  = threadIdx.x & 31;
    const int r4 = threadIdx.x >> 5;
    const int n0 = blockIdx.x * 32;
    const int k0 = blockIdx.y * 32;
#pragma unroll
    for (int i = 0; i < 4; i++)
        t[r4 + 8*i][c] = B[(size_t)(k0 + r4 + 8*i) * N + n0 + c];
    __syncthreads();
#pragma unroll
    for (int i = 0; i < 4; i++) {
        const int n = n0 + r4 + 8*i;
        const float v = t[c][r4 + 8*i];
        const __nv_bfloat16 hi = __float2bfloat16_rn(v);
        Th[(size_t)n * K + k0 + c] = hi;
        Tl[(size_t)n * K + k0 + c] = __float2bfloat16_rn(v - __bfloat162float(hi));
    }
}

// Pre-pass 2: elementwise bf16 split of activations
__global__ void __launch_bounds__(256)
asplit(const float* __restrict__ X, __nv_bfloat16* __restrict__ H,
       __nv_bfloat16* __restrict__ L)
{
    const size_t i = (size_t)blockIdx.x * 256 + threadIdx.x;
    float4 x = ((const float4*)X)[i];
    uint32_t h0, l0, h1, l1;
    split2(x.x, x.y, h0, l0);
    split2(x.z, x.w, h1, l1);
    ((uint32_t*)H)[2*i]   = h0;
    ((uint32_t*)H)[2*i+1] = h1;
    ((uint32_t*)L)[2*i]   = l0;
    ((uint32_t*)L)[2*i+1] = l1;
}

// ---------------------------------------------------------------------------
// HMMA bf16 3-product GEMM: C = A @ Bt^T + bias
// MODE 1: writes Q/K/V as bf16 hi/lo per-head using the reference's QUIRKY
//         direct reshape (bs, NH, seq, hd): flat f = sq*768 + nn maps to
//         t = sq*NH + (nn>>6); h = t>>11; s2 = t&2047; d = nn&63.
// MODE 0: fp32 C.
// ---------------------------------------------------------------------------
#define RP 24
__global__ void __launch_bounds__(256)
mma_gemm_impl(const __nv_bfloat16* __restrict__ Ahg, const __nv_bfloat16* __restrict__ Alg,
              const __nv_bfloat16* __restrict__ Bhg, const __nv_bfloat16* __restrict__ Blg,
              const float* __restrict__ bias, float* __restrict__ C,
              int N, int K, int MODE)
{
    __shared__ __nv_bfloat16 sAh[2][128*RP];
    __shared__ __nv_bfloat16 sAl[2][128*RP];
    __shared__ __nv_bfloat16 sBh[2][128*RP];
    __shared__ __nv_bfloat16 sBl[2][128*RP];

    const int tid  = threadIdx.x;
    const int wid  = tid >> 5;
    const int lane = tid & 31;
    const int wm   = wid >> 2;
    const int wn   = wid & 3;
    const int m0 = blockIdx.y * 128;
    const int n0 = blockIdx.x * 128;

    const int row  = tid >> 1;
    const int half = tid & 1;
    const __nv_bfloat16* pAh = Ahg + (size_t)(m0 + row) * K + half * 8;
    const __nv_bfloat16* pAl = Alg + (size_t)(m0 + row) * K + half * 8;
    const __nv_bfloat16* pBh = Bhg + (size_t)(n0 + row) * K + half * 8;
    const __nv_bfloat16* pBl = Blg + (size_t)(n0 + row) * K + half * 8;
    const int sdst = row * RP + half * 8;

    const uint32_t bAh = smem_u32(sAh), bAl = smem_u32(sAl);
    const uint32_t bBh = smem_u32(sBh), bBl = smem_u32(sBl);
    uint32_t a_off[4], b_off[4];
    {
        const int ar = lane & 15, ak = (lane >> 4) * 16;
        const int bn = lane & 7,  bk = ((lane >> 3) & 1) * 16;
#pragma unroll
        for (int i = 0; i < 4; i++) a_off[i] = (uint32_t)((wm*64 + i*16 + ar) * (RP*2) + ak);
#pragma unroll
        for (int j = 0; j < 4; j++) b_off[j] = (uint32_t)((wn*32 + j*8 + bn) * (RP*2) + bk);
    }

    float acc[4][4][4];
#pragma unroll
    for (int i = 0; i < 4; i++)
#pragma unroll
        for (int j = 0; j < 4; j++)
#pragma unroll
            for (int t = 0; t < 4; t++) acc[i][j][t] = 0.0f;

    const int NC = K >> 4;

    uint4 vah = *(const uint4*)pAh;
    uint4 val = *(const uint4*)pAl;
    uint4 vbh = *(const uint4*)pBh;
    uint4 vbl = *(const uint4*)pBl;
    *(uint4*)&sAh[0][sdst] = vah;
    *(uint4*)&sAl[0][sdst] = val;
    *(uint4*)&sBh[0][sdst] = vbh;
    *(uint4*)&sBl[0][sdst] = vbl;
    __syncthreads();

    for (int kc = 0; kc < NC; kc++) {
        const int buf = kc & 1;
        const uint32_t bo = (uint32_t)buf * (128*RP*2);
        if (kc + 1 < NC) {
            const int ko = (kc + 1) * 16;
            vah = *(const uint4*)(pAh + ko);
            val = *(const uint4*)(pAl + ko);
            vbh = *(const uint4*)(pBh + ko);
            vbl = *(const uint4*)(pBl + ko);
        }

        uint32_t fbh[4][2], fbl[4][2];
#pragma unroll
        for (int j = 0; j < 4; j++) {
            ldm_x2(fbh[j], bBh + bo + b_off[j]);
            ldm_x2(fbl[j], bBl + bo + b_off[j]);
        }
#pragma unroll
        for (int i = 0; i < 4; i++) {
            uint32_t fah[4], fal[4];
            ldm_x4(fah, bAh + bo + a_off[i]);
            ldm_x4(fal, bAl + bo + a_off[i]);
#pragma unroll
            for (int j = 0; j < 4; j++) {
                mma_bf16(acc[i][j], fah, fbh[j]);
                mma_bf16(acc[i][j], fah, fbl[j]);
                mma_bf16(acc[i][j], fal, fbh[j]);
            }
        }

        if (kc + 1 < NC) {
            const int so = buf ^ 1;
            *(uint4*)&sAh[so][sdst] = vah;
            *(uint4*)&sAl[so][sdst] = val;
            *(uint4*)&sBh[so][sdst] = vbh;
            *(uint4*)&sBl[so][sdst] = vbl;
        }
        __syncthreads();
    }

    const int lr = lane >> 2;
    const int lc = (lane & 3) << 1;
#pragma unroll
    for (int i = 0; i < 4; i++) {
        const int m = m0 + wm*64 + i*16 + lr;
#pragma unroll
        for (int j = 0; j < 4; j++) {
            const int n = n0 + wn*32 + j*8 + lc;
            const float b0 = bias[n], b1 = bias[n + 1];
            const float v00 = acc[i][j][0] + b0, v01 = acc[i][j][1] + b1;
            const float v10 = acc[i][j][2] + b0, v11 = acc[i][j][3] + b1;
            if (MODE == 0) {
                *(float2*)(C + (size_t)m * N + n) = make_float2(v00, v01);
                *(float2*)(C + (size_t)(m + 8) * N + n) = make_float2(v10, v11);
            } else {
                const int sect = n0 / NX;            // 0=Q,1=K,2=V
                const int nn = n - sect * NX;
                const int d  = nn & 63;
                const int b  = m >> 11;
                const int sq = m & (SEQ - 1);
                __nv_bfloat16* Hd = (sect == 0) ? g_Qh : (sect == 1) ? g_Kh : g_Vh;
                __nv_bfloat16* Ld = (sect == 0) ? g_Ql : (sect == 1) ? g_Kl : g_Vl;
                // Quirky direct reshape: t = sq*NH + nn/64 -> (h, s2)
                const int t0 = sq * NH + (nn >> 6);
                const int h0 = t0 >> 11, s20 = t0 & (SEQ - 1);
                const int t1 = (sq + 8) * NH + (nn >> 6);     // row m+8, same b
                const int h1 = t1 >> 11, s21 = t1 & (SEQ - 1);
                const size_t base0 = ((size_t)(b*NH + h0) * SEQ + s20) * HD + d;
                const size_t base1 = ((size_t)(b*NH + h1) * SEQ + s21) * HD + d;
                uint32_t hi0, lo0, hi1, lo1;
                split2(v00, v01, hi0, lo0);
                split2(v10, v11, hi1, lo1);
                *(uint32_t*)(Hd + base0) = hi0;
                *(uint32_t*)(Ld + base0) = lo0;
                *(uint32_t*)(Hd + base1) = hi1;
                *(uint32_t*)(Ld + base1) = lo1;
            }
        }
    }
}

// ---------------------------------------------------------------------------
// HMMA flash attention: q-tile 128, k-tile 64, 8 warps x 16 q-rows.
// S and P@V both bf16 3-product; softmax warp-local (4-lane shfl).
// K/V tiles in static smem, rows padded to 72 bf16 (144 B) -> conflict-free.
// q/k indices are head-view indices (quirky reshape), matching the reference.
// ---------------------------------------------------------------------------
#define ARP 72
#define ARPB (ARP*2)
__global__ void __launch_bounds__(256)
attn_mma(const float* __restrict__ amask)
{
    __shared__ __nv_bfloat16 sKh[64*ARP], sKl[64*ARP];
    __shared__ __nv_bfloat16 sVh[64*ARP], sVl[64*ARP];

    const int tid  = threadIdx.x;
    const int wid  = tid >> 5;
    const int lane = tid & 31;
    const int qb = gridDim.x - 1 - blockIdx.x;   // long CTAs first
    const int h  = blockIdx.y;
    const int b  = blockIdx.z;
    const int q0 = qb * 128;
    const int qw = q0 + wid * 16;                // warp's 16 q-rows

    const size_t hoff = (size_t)(b*NH + h) * SEQ * HD;
    const __nv_bfloat16* Qh = g_Qh + hoff;
    const __nv_bfloat16* Ql = g_Ql + hoff;
    const __nv_bfloat16* Kh = g_Kh + hoff;
    const __nv_bfloat16* Kl = g_Kl + hoff;
    const __nv_bfloat16* Vh = g_Vh + hoff;
    const __nv_bfloat16* Vl = g_Vl + hoff;
    const float* am = amask + (size_t)b * SEQ;

    const int r  = lane >> 2;          // 0..7
    const int c2 = (lane & 3) << 1;    // 0,2,4,6

    // Q fragments direct from gmem (A-frag element map: a_t at
    // (row r + (t&1)*8, col ds*16 + c2 + (t>>1)*8), 2 consecutive d)
    uint32_t fqh[4][4], fql[4][4];
#pragma unroll
    for (int ds = 0; ds < 4; ds++)
#pragma unroll
        for (int t = 0; t < 4; t++) {
            const int rr = qw + r + (t & 1) * 8;
            const int dd = ds * 16 + c2 + (t >> 1) * 8;
            fqh[ds][t] = *(const uint32_t*)(Qh + (size_t)rr * HD + dd);
            fql[ds][t] = *(const uint32_t*)(Ql + (size_t)rr * HD + dd);
        }

    float acc[8][4];
#pragma unroll
    for (int j = 0; j < 8; j++)
#pragma unroll
        for (int t = 0; t < 4; t++) acc[j][t] = 0.0f;
    float mrow0 = -3.0e38f, mrow1 = -3.0e38f, lrow0 = 0.0f, lrow1 = 0.0f;

    // smem addresses
    const uint32_t bKh = smem_u32(sKh), bKl = smem_u32(sKl);
    const uint32_t bVh = smem_u32(sVh), bVl = smem_u32(sVl);
    uint32_t kb_off[8];
#pragma unroll
    for (int j = 0; j < 8; j++)
        kb_off[j] = (uint32_t)((j*8 + (lane & 7)) * ARPB + ((lane >> 3) & 1) * 16);
    const uint32_t vt_base = (uint32_t)((lane & 15) * ARPB);

    // tile loaders: FULL coverage — 64 rows x 64 cols, 2 uint4 per thread per
    // array.  row = tid>>3 (0..31, then +32), col = (tid&7)*8 (0..56).
    const int trow = tid >> 3;
    const int tcol = (tid & 7) << 3;

    const int nkb = 2 * qb + 2;
    const int qr0 = qw + r, qr1 = qw + r + 8;

    for (int kb = 0; kb < nkb; kb++) {
        const int k0 = kb * 64;
        __syncthreads();
#pragma unroll
        for (int it = 0; it < 2; it++) {
            const int rr = trow + it * 32;
            const size_t src = (size_t)(k0 + rr) * HD + tcol;
            const int dst = rr * ARP + tcol;
            *(uint4*)&sKh[dst] = *(const uint4*)(Kh + src);
            *(uint4*)&sKl[dst] = *(const uint4*)(Kl + src);
            *(uint4*)&sVh[dst] = *(const uint4*)(Vh + src);
            *(uint4*)&sVl[dst] = *(const uint4*)(Vl + src);
        }
        __syncthreads();

        // S = Q @ K^T (3-product)
        float s[8][4];
#pragma unroll
        for (int j = 0; j < 8; j++)
#pragma unroll
            for (int t = 0; t < 4; t++) s[j][t] = 0.0f;
#pragma unroll
        for (int ds = 0; ds < 4; ds++) {
            uint32_t fkh[8][2], fkl[8][2];
#pragma unroll
            for (int j = 0; j < 8; j++) {
                ldm_x2(fkh[j], bKh + kb_off[j] + ds * 32);
                ldm_x2(fkl[j], bKl + kb_off[j] + ds * 32);
            }
#pragma unroll
            for (int j = 0; j < 8; j++) {
                mma_bf16(s[j], fqh[ds], fkh[j]);
                mma_bf16(s[j], fqh[ds], fkl[j]);
                mma_bf16(s[j], fql[ds], fkh[j]);
            }
        }

        // mask + online softmax (rows qr0, qr1)
        float rmax0 = -3.0e38f, rmax1 = -3.0e38f;
#pragma unroll
        for (int j = 0; j < 8; j++) {
            const int k = k0 + j*8 + c2;
            const float2 amv = *(const float2*)(am + k);
            s[j][0] = (k   <= qr0) ? s[j][0]*0.125f + amv.x : -10000.0f + amv.x;
            s[j][1] = (k+1 <= qr0) ? s[j][1]*0.125f + amv.y : -10000.0f + amv.y;
            s[j][2] = (k   <= qr1) ? s[j][2]*0.125f + amv.x : -10000.0f + amv.x;
            s[j][3] = (k+1 <= qr1) ? s[j][3]*0.125f + amv.y : -10000.0f + amv.y;
            rmax0 = fmaxf(rmax0, fmaxf(s[j][0], s[j][1]));
            rmax1 = fmaxf(rmax1, fmaxf(s[j][2], s[j][3]));
        }
        rmax0 = fmaxf(rmax0, __shfl_xor_sync(0xffffffffu, rmax0, 1));
        rmax0 = fmaxf(rmax0, __shfl_xor_sync(0xffffffffu, rmax0, 2));
        rmax1 = fmaxf(rmax1, __shfl_xor_sync(0xffffffffu, rmax1, 1));
        rmax1 = fmaxf(rmax1, __shfl_xor_sync(0xffffffffu, rmax1, 2));
        const float mnew0 = fmaxf(mrow0, rmax0);
        const float mnew1 = fmaxf(mrow1, rmax1);
        const float corr0 = __expf(mrow0 - mnew0);
        const float corr1 = __expf(mrow1 - mnew1);
        float rsum0 = 0.0f, rsum1 = 0.0f;
#pragma unroll
        for (int j = 0; j < 8; j++) {
            s[j][0] = __expf(s[j][0] - mnew0);
            s[j][1] = __expf(s[j][1] - mnew0);
            s[j][2] = __expf(s[j][2] - mnew1);
            s[j][3] = __expf(s[j][3] - mnew1);
            rsum0 += s[j][0] + s[j][1];
            rsum1 += s[j][2] + s[j][3];
        }
        rsum0 += __shfl_xor_sync(0xffffffffu, rsum0, 1);
        rsum0 += __shfl_xor_sync(0xffffffffu, rsum0, 2);
        rsum1 += __shfl_xor_sync(0xffffffffu, rsum1, 1);
        rsum1 += __shfl_xor_sync(0xffffffffu, rsum1, 2);
        lrow0 = lrow0 * corr0 + rsum0;
        lrow1 = lrow1 * corr1 + rsum1;
        mrow0 = mnew0; mrow1 = mnew1;
#pragma unroll
        for (int j = 0; j < 8; j++) {
            acc[j][0] *= corr0; acc[j][1] *= corr0;
            acc[j][2] *= corr1; acc[j][3] *= corr1;
        }

        // P fragments (register repack: A-frag t from S n-frags 2t, 2t+1)
        uint32_t fph[4][4], fpl[4][4];
#pragma unroll
        for (int t = 0; t < 4; t++) {
            split2(s[2*t][0],   s[2*t][1],   fph[t][0], fpl[t][0]);
            split2(s[2*t][2],   s[2*t][3],   fph[t][1], fpl[t][1]);
            split2(s[2*t+1][0], s[2*t+1][1], fph[t][2], fpl[t][2]);
            split2(s[2*t+1][2], s[2*t+1][3], fph[t][3], fpl[t][3]);
        }

        // O += P @ V (3-product; V B-frags via ldmatrix.trans)
#pragma unroll
        for (int t = 0; t < 4; t++) {
            const uint32_t ro = vt_base + (uint32_t)(t * 16 * ARPB);
#pragma unroll
            for (int dn = 0; dn < 8; dn++) {
                uint32_t fvh[2], fvl[2];
                ldm_x2t(fvh, bVh + ro + dn * 16);
                ldm_x2t(fvl, bVl + ro + dn * 16);
                mma_bf16(acc[dn], fph[t], fvh);
                mma_bf16(acc[dn], fph[t], fvl);
                mma_bf16(acc[dn], fpl[t], fvh);
            }
        }
    }

    // epilogue: normalize, bf16 hi/lo split into g_Ah/g_Al at [b, q_view, h*64+d]
    const float inv0 = 1.0f / lrow0;
    const float inv1 = 1.0f / lrow1;
#pragma unroll
    for (int dn = 0; dn < 8; dn++) {
        const int d = dn*8 + c2;
        uint32_t hi0, lo0, hi1, lo1;
        split2(acc[dn][0]*inv0, acc[dn][1]*inv0, hi0, lo0);
        split2(acc[dn][2]*inv1, acc[dn][3]*inv1, hi1, lo1);
        const size_t i0 = ((size_t)b * SEQ + qr0) * NX + h * HD + d;
        const size_t i1 = ((size_t)b * SEQ + qr1) * NX + h * HD + d;
        *(uint32_t*)(g_Ah + i0) = hi0;
        *(uint32_t*)(g_Al + i0) = lo0;
        *(uint32_t*)(g_Ah + i1) = hi1;
        *(uint32_t*)(g_Al + i1) = lo1;
    }
}

// ---------------------------------------------------------------------------
extern "C" void kernel_launch(void* const* d_in, const int* in_sizes, int n_in,
                              void* d_out, int out_size)
{
    const float* hidden = (const float*)d_in[0];
    const float* amask  = (const float*)d_in[1];
    const float* w_attn = (const float*)d_in[2];
    const float* b_attn = (const float*)d_in[3];
    const float* w_proj = (const float*)d_in[4];
    const float* b_proj = (const float*)d_in[5];
    float* out = (float*)d_out;

    __nv_bfloat16 *Bh1, *Bl1, *Bh2, *Bl2, *Ah, *Al;
    cudaGetSymbolAddress((void**)&Bh1, g_Bh1);
    cudaGetSymbolAddress((void**)&Bl1, g_Bl1);
    cudaGetSymbolAddress((void**)&Bh2, g_Bh2);
    cudaGetSymbolAddress((void**)&Bl2, g_Bl2);
    cudaGetSymbolAddress((void**)&Ah,  g_Ah);
    cudaGetSymbolAddress((void**)&Al,  g_Al);

    // Pre-pass: transpose+split weights, split activations
    wsplitT<<<dim3(NQKV/32, NX/32), 256>>>(w_attn, Bh1, Bl1, NX, NQKV);
    wsplitT<<<dim3(NX/32,   NX/32), 256>>>(w_proj, Bh2, Bl2, NX, NX);
    asplit<<<(MROWS*NX)/(256*4), 256>>>(hidden, Ah, Al);

    // 1) QKV = X @ W_attn + b -> bf16 hi/lo Q/K/V, quirky per-head layout
    mma_gemm_impl<<<dim3(NQKV/128, MROWS/128), 256>>>(
        Ah, Al, Bh1, Bl1, b_attn, nullptr, NQKV, NX, 1);

    // 2) HMMA flash attention -> bf16 hi/lo activations
    attn_mma<<<dim3(SEQ/128, NH, BSZ), 256>>>(amask);

    // 3) out = A @ W_proj + b
    mma_gemm_impl<<<dim3(NX/128, MROWS/128), 256>>>(
        Ah, Al, Bh2, Bl2, b_proj, out, NX, NX, 0);
}

// round 10
// speedup vs baseline: 2.6225x; 1.0521x over previous
#include <cuda_runtime.h>
#include <cuda_bf16.h>
#include <math.h>
#include <stdint.h>

#define BSZ 2
#define SEQ 2048
#define NX 768
#define NH 12
#define HD 64
#define MROWS (BSZ*SEQ)      // 4096
#define NQKV (3*NX)          // 2304

// Scratch (no cudaMalloc allowed)
__device__ __nv_bfloat16 g_Qh[BSZ*NH*SEQ*HD];
__device__ __nv_bfloat16 g_Ql[BSZ*NH*SEQ*HD];
__device__ __nv_bfloat16 g_Kh[BSZ*NH*SEQ*HD];
__device__ __nv_bfloat16 g_Kl[BSZ*NH*SEQ*HD];
__device__ __nv_bfloat16 g_Vh[BSZ*NH*SEQ*HD];
__device__ __nv_bfloat16 g_Vl[BSZ*NH*SEQ*HD];
__device__ __nv_bfloat16 g_Ah[BSZ*SEQ*NX];   // attn out hi (feeds proj)
__device__ __nv_bfloat16 g_Al[BSZ*SEQ*NX];   // attn out lo
__device__ __nv_bfloat16 g_Bh1[NQKV*NX];     // w_attn^T hi  [2304][768]
__device__ __nv_bfloat16 g_Bl1[NQKV*NX];
__device__ __nv_bfloat16 g_Bh2[NX*NX];       // w_proj^T hi  [768][768]
__device__ __nv_bfloat16 g_Bl2[NX*NX];

// ---------------------------------------------------------------------------
// helpers
// ---------------------------------------------------------------------------
__device__ __forceinline__ uint32_t smem_u32(const void* p) {
    uint32_t a;
    asm("{ .reg .u64 t; cvta.to.shared.u64 t, %1; cvt.u32.u64 %0, t; }"
        : "=r"(a) : "l"(p));
    return a;
}
__device__ __forceinline__ void mma_bf16(float* d, const uint32_t* a, const uint32_t* b) {
    asm volatile(
        "mma.sync.aligned.m16n8k16.row.col.f32.bf16.bf16.f32 "
        "{%0,%1,%2,%3}, {%4,%5,%6,%7}, {%8,%9}, {%0,%1,%2,%3};"
        : "+f"(d[0]), "+f"(d[1]), "+f"(d[2]), "+f"(d[3])
        : "r"(a[0]), "r"(a[1]), "r"(a[2]), "r"(a[3]), "r"(b[0]), "r"(b[1]));
}
__device__ __forceinline__ void ldm_x4(uint32_t* r, uint32_t addr) {
    asm volatile("ldmatrix.sync.aligned.m8n8.x4.shared.b16 {%0,%1,%2,%3}, [%4];"
                 : "=r"(r[0]), "=r"(r[1]), "=r"(r[2]), "=r"(r[3]) : "r"(addr));
}
__device__ __forceinline__ void ldm_x2(uint32_t* r, uint32_t addr) {
    asm volatile("ldmatrix.sync.aligned.m8n8.x2.shared.b16 {%0,%1}, [%2];"
                 : "=r"(r[0]), "=r"(r[1]) : "r"(addr));
}
__device__ __forceinline__ void ldm_x2t(uint32_t* r, uint32_t addr) {
    asm volatile("ldmatrix.sync.aligned.m8n8.x2.trans.shared.b16 {%0,%1}, [%2];"
                 : "=r"(r[0]), "=r"(r[1]) : "r"(addr));
}
__device__ __forceinline__ void cp_async16(uint32_t dst, const void* src) {
    asm volatile("cp.async.cg.shared.global [%0], [%1], 16;"
                 :: "r"(dst), "l"(src) : "memory");
}
__device__ __forceinline__ void cp_commit() {
    asm volatile("cp.async.commit_group;" ::: "memory");
}
__device__ __forceinline__ void cp_wait0() {
    asm volatile("cp.async.wait_group 0;" ::: "memory");
}
// split two fp32 into packed bf16 hi2 / lo2
__device__ __forceinline__ void split2(float a, float b, uint32_t& hi, uint32_t& lo) {
    __nv_bfloat16 ha = __float2bfloat16_rn(a), hb = __float2bfloat16_rn(b);
    __nv_bfloat16 la = __float2bfloat16_rn(a - __bfloat162float(ha));
    __nv_bfloat16 lb = __float2bfloat16_rn(b - __bfloat162float(hb));
    __nv_bfloat162 H(ha, hb), L(la, lb);
    hi = *(uint32_t*)&H; lo = *(uint32_t*)&L;
}

// ---------------------------------------------------------------------------
// Pre-pass 1: transpose + bf16-split weights.  B[K,N] fp32 -> Th/Tl [N][K]
// ---------------------------------------------------------------------------
__global__ void __launch_bounds__(256)
wsplitT(const float* __restrict__ B, __nv_bfloat16* __restrict__ Th,
        __nv_bfloat16* __restrict__ Tl, int K, int N)
{
    __shared__ float t[32][33];
    const int c  = threadIdx.x & 31;
    const int r4 = threadIdx.x >> 5;
    const int n0 = blockIdx.x * 32;
    const int k0 = blockIdx.y * 32;
#pragma unroll
    for (int i = 0; i < 4; i++)
        t[r4 + 8*i][c] = B[(size_t)(k0 + r4 + 8*i) * N + n0 + c];
    __syncthreads();
#pragma unroll
    for (int i = 0; i < 4; i++) {
        const int n = n0 + r4 + 8*i;
        const float v = t[c][r4 + 8*i];
        const __nv_bfloat16 hi = __float2bfloat16_rn(v);
        Th[(size_t)n * K + k0 + c] = hi;
        Tl[(size_t)n * K + k0 + c] = __float2bfloat16_rn(v - __bfloat162float(hi));
    }
}

// Pre-pass 2: elementwise bf16 split of activations
__global__ void __launch_bounds__(256)
asplit(const float* __restrict__ X, __nv_bfloat16* __restrict__ H,
       __nv_bfloat16* __restrict__ L)
{
    const size_t i = (size_t)blockIdx.x * 256 + threadIdx.x;
    float4 x = ((const float4*)X)[i];
    uint32_t h0, l0, h1, l1;
    split2(x.x, x.y, h0, l0);
    split2(x.z, x.w, h1, l1);
    ((uint32_t*)H)[2*i]   = h0;
    ((uint32_t*)H)[2*i+1] = h1;
    ((uint32_t*)L)[2*i]   = l0;
    ((uint32_t*)L)[2*i+1] = l1;
}

// ---------------------------------------------------------------------------
// HMMA bf16 3-product GEMM: C = A @ Bt^T + bias
// cp.async 2-stage pipeline, 2 CTAs/SM (reg cap 128).
// MODE 1: writes Q/K/V bf16 hi/lo via the reference's QUIRKY direct reshape:
//         flat f = sq*768 + nn -> t = sq*NH + (nn>>6); h = t>>11; s2 = t&2047.
// MODE 0: fp32 C.
// ---------------------------------------------------------------------------
#define RP 24
#define GBUF (128*RP*2)      // bytes per buffer per array
__global__ void __launch_bounds__(256, 2)
mma_gemm_impl(const __nv_bfloat16* __restrict__ Ahg, const __nv_bfloat16* __restrict__ Alg,
              const __nv_bfloat16* __restrict__ Bhg, const __nv_bfloat16* __restrict__ Blg,
              const float* __restrict__ bias, float* __restrict__ C,
              int N, int K, int MODE)
{
    __shared__ __nv_bfloat16 sAh[2][128*RP];
    __shared__ __nv_bfloat16 sAl[2][128*RP];
    __shared__ __nv_bfloat16 sBh[2][128*RP];
    __shared__ __nv_bfloat16 sBl[2][128*RP];

    const int tid  = threadIdx.x;
    const int wid  = tid >> 5;
    const int lane = tid & 31;
    const int wm   = wid >> 2;
    const int wn   = wid & 3;
    const int m0 = blockIdx.y * 128;
    const int n0 = blockIdx.x * 128;

    const int row  = tid >> 1;
    const int half = tid & 1;
    const __nv_bfloat16* pAh = Ahg + (size_t)(m0 + row) * K + half * 8;
    const __nv_bfloat16* pAl = Alg + (size_t)(m0 + row) * K + half * 8;
    const __nv_bfloat16* pBh = Bhg + (size_t)(n0 + row) * K + half * 8;
    const __nv_bfloat16* pBl = Blg + (size_t)(n0 + row) * K + half * 8;
    const uint32_t sdb = (uint32_t)((row * RP + half * 8) * 2);   // byte offset

    const uint32_t bAh = smem_u32(sAh), bAl = smem_u32(sAl);
    const uint32_t bBh = smem_u32(sBh), bBl = smem_u32(sBl);
    uint32_t a_off[4], b_off[4];
    {
        const int ar = lane & 15, ak = (lane >> 4) * 16;
        const int bn = lane & 7,  bk = ((lane >> 3) & 1) * 16;
#pragma unroll
        for (int i = 0; i < 4; i++) a_off[i] = (uint32_t)((wm*64 + i*16 + ar) * (RP*2) + ak);
#pragma unroll
        for (int j = 0; j < 4; j++) b_off[j] = (uint32_t)((wn*32 + j*8 + bn) * (RP*2) + bk);
    }

    float acc[4][4][4];
#pragma unroll
    for (int i = 0; i < 4; i++)
#pragma unroll
        for (int j = 0; j < 4; j++)
#pragma unroll
            for (int t = 0; t < 4; t++) acc[i][j][t] = 0.0f;

    const int NC = K >> 4;

    // prologue: chunk 0 -> buf 0
    {
        cp_async16(bAh + sdb, pAh);
        cp_async16(bAl + sdb, pAl);
        cp_async16(bBh + sdb, pBh);
        cp_async16(bBl + sdb, pBl);
        cp_commit();
    }

    for (int kc = 0; kc < NC; kc++) {
        const int buf = kc & 1;
        const uint32_t bo = (uint32_t)buf * GBUF;
        cp_wait0();
        __syncthreads();                    // chunk kc visible; buf^1 reads done
        if (kc + 1 < NC) {
            const int ko = (kc + 1) * 16;
            const uint32_t dq = (uint32_t)(buf ^ 1) * GBUF + sdb;
            cp_async16(bAh + dq, pAh + ko);
            cp_async16(bAl + dq, pAl + ko);
            cp_async16(bBh + dq, pBh + ko);
            cp_async16(bBl + dq, pBl + ko);
            cp_commit();
        }

        uint32_t fbh[4][2], fbl[4][2];
#pragma unroll
        for (int j = 0; j < 4; j++) {
            ldm_x2(fbh[j], bBh + bo + b_off[j]);
            ldm_x2(fbl[j], bBl + bo + b_off[j]);
        }
#pragma unroll
        for (int i = 0; i < 4; i++) {
            uint32_t fah[4], fal[4];
            ldm_x4(fah, bAh + bo + a_off[i]);
            ldm_x4(fal, bAl + bo + a_off[i]);
#pragma unroll
            for (int j = 0; j < 4; j++) {
                mma_bf16(acc[i][j], fah, fbh[j]);
                mma_bf16(acc[i][j], fah, fbl[j]);
                mma_bf16(acc[i][j], fal, fbh[j]);
            }
        }
    }

    const int lr = lane >> 2;
    const int lc = (lane & 3) << 1;
#pragma unroll
    for (int i = 0; i < 4; i++) {
        const int m = m0 + wm*64 + i*16 + lr;
#pragma unroll
        for (int j = 0; j < 4; j++) {
            const int n = n0 + wn*32 + j*8 + lc;
            const float b0 = bias[n], b1 = bias[n + 1];
            const float v00 = acc[i][j][0] + b0, v01 = acc[i][j][1] + b1;
            const float v10 = acc[i][j][2] + b0, v11 = acc[i][j][3] + b1;
            if (MODE == 0) {
                *(float2*)(C + (size_t)m * N + n) = make_float2(v00, v01);
                *(float2*)(C + (size_t)(m + 8) * N + n) = make_float2(v10, v11);
            } else {
                const int sect = n0 / NX;            // 0=Q,1=K,2=V
                const int nn = n - sect * NX;
                const int d  = nn & 63;
                const int b  = m >> 11;
                const int sq = m & (SEQ - 1);
                __nv_bfloat16* Hd = (sect == 0) ? g_Qh : (sect == 1) ? g_Kh : g_Vh;
                __nv_bfloat16* Ld = (sect == 0) ? g_Ql : (sect == 1) ? g_Kl : g_Vl;
                // Quirky direct reshape: t = sq*NH + nn/64 -> (h, s2)
                const int t0 = sq * NH + (nn >> 6);
                const int h0 = t0 >> 11, s20 = t0 & (SEQ - 1);
                const int t1 = (sq + 8) * NH + (nn >> 6);     // row m+8, same b
                const int h1 = t1 >> 11, s21 = t1 & (SEQ - 1);
                const size_t base0 = ((size_t)(b*NH + h0) * SEQ + s20) * HD + d;
                const size_t base1 = ((size_t)(b*NH + h1) * SEQ + s21) * HD + d;
                uint32_t hi0, lo0, hi1, lo1;
                split2(v00, v01, hi0, lo0);
                split2(v10, v11, hi1, lo1);
                *(uint32_t*)(Hd + base0) = hi0;
                *(uint32_t*)(Ld + base0) = lo0;
                *(uint32_t*)(Hd + base1) = hi1;
                *(uint32_t*)(Ld + base1) = lo1;
            }
        }
    }
}

// ---------------------------------------------------------------------------
// HMMA flash attention: q-tile 128, k-tile 64, 8 warps x 16 q-rows.
// cp.async double-buffered K/V (72 KB dynamic smem), ONE sync per k-tile
// (compute phase has no smem writes; P stays in registers).
// ---------------------------------------------------------------------------
#define ARP 72
#define ARPB (ARP*2)
#define ATILE (64*ARP*2)            // 9216 B per array per buffer
#define ASTRIDE (2*ATILE)           // both buffers of one array
#define ATTN_SMEM (4*ASTRIDE)       // 73728 B

__global__ void __launch_bounds__(256)
attn_mma(const float* __restrict__ amask)
{
    extern __shared__ __nv_bfloat16 dynsm[];

    const int tid  = threadIdx.x;
    const int wid  = tid >> 5;
    const int lane = tid & 31;
    const int qb = gridDim.x - 1 - blockIdx.x;   // long CTAs first
    const int h  = blockIdx.y;
    const int b  = blockIdx.z;
    const int q0 = qb * 128;
    const int qw = q0 + wid * 16;                // warp's 16 q-rows

    const size_t hoff = (size_t)(b*NH + h) * SEQ * HD;
    const __nv_bfloat16* Qh = g_Qh + hoff;
    const __nv_bfloat16* Ql = g_Ql + hoff;
    const __nv_bfloat16* Kh = g_Kh + hoff;
    const __nv_bfloat16* Kl = g_Kl + hoff;
    const __nv_bfloat16* Vh = g_Vh + hoff;
    const __nv_bfloat16* Vl = g_Vl + hoff;
    const float* am = amask + (size_t)b * SEQ;

    const int r  = lane >> 2;          // 0..7
    const int c2 = (lane & 3) << 1;    // 0,2,4,6

    const uint32_t sm0 = smem_u32(dynsm);
    const uint32_t bKh = sm0;
    const uint32_t bKl = sm0 + ASTRIDE;
    const uint32_t bVh = sm0 + 2*ASTRIDE;
    const uint32_t bVl = sm0 + 3*ASTRIDE;

    // Q fragments direct from gmem (A-frag map: a_t at
    // (row r + (t&1)*8, col ds*16 + c2 + (t>>1)*8))
    uint32_t fqh[4][4], fql[4][4];
#pragma unroll
    for (int ds = 0; ds < 4; ds++)
#pragma unroll
        for (int t = 0; t < 4; t++) {
            const int rr = qw + r + (t & 1) * 8;
            const int dd = ds * 16 + c2 + (t >> 1) * 8;
            fqh[ds][t] = *(const uint32_t*)(Qh + (size_t)rr * HD + dd);
            fql[ds][t] = *(const uint32_t*)(Ql + (size_t)rr * HD + dd);
        }

    float acc[8][4];
#pragma unroll
    for (int j = 0; j < 8; j++)
#pragma unroll
        for (int t = 0; t < 4; t++) acc[j][t] = 0.0f;
    float mrow0 = -3.0e38f, mrow1 = -3.0e38f, lrow0 = 0.0f, lrow1 = 0.0f;

    uint32_t kb_off[8];
#pragma unroll
    for (int j = 0; j < 8; j++)
        kb_off[j] = (uint32_t)((j*8 + (lane & 7)) * ARPB + ((lane >> 3) & 1) * 16);
    const uint32_t vt_base = (uint32_t)((lane & 15) * ARPB);

    // tile loaders: full 64x64 coverage, 2 x 16B per thread per array
    const int trow = tid >> 3;
    const int tcol = (tid & 7) << 3;
    const uint32_t tdst = (uint32_t)(trow * ARPB + tcol * 2);

    const int nkb = 2 * qb + 2;
    const int qr0 = qw + r, qr1 = qw + r + 8;

    // prologue: tile 0 -> buf 0
#pragma unroll
    for (int it = 0; it < 2; it++) {
        const int rr = trow + it * 32;
        const size_t src = (size_t)rr * HD + tcol;
        const uint32_t dst = tdst + (uint32_t)(it * 32 * ARPB);
        cp_async16(bKh + dst, Kh + src);
        cp_async16(bKl + dst, Kl + src);
        cp_async16(bVh + dst, Vh + src);
        cp_async16(bVl + dst, Vl + src);
    }
    cp_commit();

    for (int kb = 0; kb < nkb; kb++) {
        const int k0 = kb * 64;
        const uint32_t bo = (uint32_t)(kb & 1) * ATILE;
        cp_wait0();
        __syncthreads();                 // tile kb visible; buf^1 reads done
        if (kb + 1 < nkb) {
            const int kn = k0 + 64;
            const uint32_t bq = (uint32_t)((kb + 1) & 1) * ATILE;
#pragma unroll
            for (int it = 0; it < 2; it++) {
                const int rr = trow + it * 32;
                const size_t src = (size_t)(kn + rr) * HD + tcol;
                const uint32_t dst = bq + tdst + (uint32_t)(it * 32 * ARPB);
                cp_async16(bKh + dst, Kh + src);
                cp_async16(bKl + dst, Kl + src);
                cp_async16(bVh + dst, Vh + src);
                cp_async16(bVl + dst, Vl + src);
            }
            cp_commit();
        }

        // S = Q @ K^T (3-product)
        float s[8][4];
#pragma unroll
        for (int j = 0; j < 8; j++)
#pragma unroll
            for (int t = 0; t < 4; t++) s[j][t] = 0.0f;
#pragma unroll
        for (int ds = 0; ds < 4; ds++) {
            uint32_t fkh[8][2], fkl[8][2];
#pragma unroll
            for (int j = 0; j < 8; j++) {
                ldm_x2(fkh[j], bKh + bo + kb_off[j] + ds * 32);
                ldm_x2(fkl[j], bKl + bo + kb_off[j] + ds * 32);
            }
#pragma unroll
            for (int j = 0; j < 8; j++) {
                mma_bf16(s[j], fqh[ds], fkh[j]);
                mma_bf16(s[j], fqh[ds], fkl[j]);
                mma_bf16(s[j], fql[ds], fkh[j]);
            }
        }

        // mask + online softmax (rows qr0, qr1)
        float rmax0 = -3.0e38f, rmax1 = -3.0e38f;
#pragma unroll
        for (int j = 0; j < 8; j++) {
            const int k = k0 + j*8 + c2;
            const float2 amv = *(const float2*)(am + k);
            s[j][0] = (k   <= qr0) ? s[j][0]*0.125f + amv.x : -10000.0f + amv.x;
            s[j][1] = (k+1 <= qr0) ? s[j][1]*0.125f + amv.y : -10000.0f + amv.y;
            s[j][2] = (k   <= qr1) ? s[j][2]*0.125f + amv.x : -10000.0f + amv.x;
            s[j][3] = (k+1 <= qr1) ? s[j][3]*0.125f + amv.y : -10000.0f + amv.y;
            rmax0 = fmaxf(rmax0, fmaxf(s[j][0], s[j][1]));
            rmax1 = fmaxf(rmax1, fmaxf(s[j][2], s[j][3]));
        }
        rmax0 = fmaxf(rmax0, __shfl_xor_sync(0xffffffffu, rmax0, 1));
        rmax0 = fmaxf(rmax0, __shfl_xor_sync(0xffffffffu, rmax0, 2));
        rmax1 = fmaxf(rmax1, __shfl_xor_sync(0xffffffffu, rmax1, 1));
        rmax1 = fmaxf(rmax1, __shfl_xor_sync(0xffffffffu, rmax1, 2));
        const float mnew0 = fmaxf(mrow0, rmax0);
        const float mnew1 = fmaxf(mrow1, rmax1);
        const float corr0 = __expf(mrow0 - mnew0);
        const float corr1 = __expf(mrow1 - mnew1);
        float rsum0 = 0.0f, rsum1 = 0.0f;
#pragma unroll
        for (int j = 0; j < 8; j++) {
            s[j][0] = __expf(s[j][0] - mnew0);
            s[j][1] = __expf(s[j][1] - mnew0);
            s[j][2] = __expf(s[j][2] - mnew1);
            s[j][3] = __expf(s[j][3] - mnew1);
            rsum0 += s[j][0] + s[j][1];
            rsum1 += s[j][2] + s[j][3];
        }
        rsum0 += __shfl_xor_sync(0xffffffffu, rsum0, 1);
        rsum0 += __shfl_xor_sync(0xffffffffu, rsum0, 2);
        rsum1 += __shfl_xor_sync(0xffffffffu, rsum1, 1);
        rsum1 += __shfl_xor_sync(0xffffffffu, rsum1, 2);
        lrow0 = lrow0 * corr0 + rsum0;
        lrow1 = lrow1 * corr1 + rsum1;
        mrow0 = mnew0; mrow1 = mnew1;
#pragma unroll
        for (int j = 0; j < 8; j++) {
            acc[j][0] *= corr0; acc[j][1] *= corr0;
            acc[j][2] *= corr1; acc[j][3] *= corr1;
        }

        // P fragments (register repack: A-frag t from S n-frags 2t, 2t+1)
        uint32_t fph[4][4], fpl[4][4];
#pragma unroll
        for (int t = 0; t < 4; t++) {
            split2(s[2*t][0],   s[2*t][1],   fph[t][0], fpl[t][0]);
            split2(s[2*t][2],   s[2*t][3],   fph[t][1], fpl[t][1]);
            split2(s[2*t+1][0], s[2*t+1][1], fph[t][2], fpl[t][2]);
            split2(s[2*t+1][2], s[2*t+1][3], fph[t][3], fpl[t][3]);
        }

        // O += P @ V (3-product; V B-frags via ldmatrix.trans)
#pragma unroll
        for (int t = 0; t < 4; t++) {
            const uint32_t ro = bo + vt_base + (uint32_t)(t * 16 * ARPB);
#pragma unroll
            for (int dn = 0; dn < 8; dn++) {
                uint32_t fvh[2], fvl[2];
                ldm_x2t(fvh, bVh + ro + dn * 16);
                ldm_x2t(fvl, bVl + ro + dn * 16);
                mma_bf16(acc[dn], fph[t], fvh);
                mma_bf16(acc[dn], fph[t], fvl);
                mma_bf16(acc[dn], fpl[t], fvh);
            }
        }
    }

    // epilogue: normalize, bf16 hi/lo split into g_Ah/g_Al at [b, q_view, h*64+d]
    const float inv0 = 1.0f / lrow0;
    const float inv1 = 1.0f / lrow1;
#pragma unroll
    for (int dn = 0; dn < 8; dn++) {
        const int d = dn*8 + c2;
        uint32_t hi0, lo0, hi1, lo1;
        split2(acc[dn][0]*inv0, acc[dn][1]*inv0, hi0, lo0);
        split2(acc[dn][2]*inv1, acc[dn][3]*inv1, hi1, lo1);
        const size_t i0 = ((size_t)b * SEQ + qr0) * NX + h * HD + d;
        const size_t i1 = ((size_t)b * SEQ + qr1) * NX + h * HD + d;
        *(uint32_t*)(g_Ah + i0) = hi0;
        *(uint32_t*)(g_Al + i0) = lo0;
        *(uint32_t*)(g_Ah + i1) = hi1;
        *(uint32_t*)(g_Al + i1) = lo1;
    }
}

// ---------------------------------------------------------------------------
extern "C" void kernel_launch(void* const* d_in, const int* in_sizes, int n_in,
                              void* d_out, int out_size)
{
    const float* hidden = (const float*)d_in[0];
    const float* amask  = (const float*)d_in[1];
    const float* w_attn = (const float*)d_in[2];
    const float* b_attn = (const float*)d_in[3];
    const float* w_proj = (const float*)d_in[4];
    const float* b_proj = (const float*)d_in[5];
    float* out = (float*)d_out;

    // Host-side attribute set: not a stream op, graph-capture-safe, idempotent.
    cudaFuncSetAttribute(attn_mma, cudaFuncAttributeMaxDynamicSharedMemorySize,
                         ATTN_SMEM);

    __nv_bfloat16 *Bh1, *Bl1, *Bh2, *Bl2, *Ah, *Al;
    cudaGetSymbolAddress((void**)&Bh1, g_Bh1);
    cudaGetSymbolAddress((void**)&Bl1, g_Bl1);
    cudaGetSymbolAddress((void**)&Bh2, g_Bh2);
    cudaGetSymbolAddress((void**)&Bl2, g_Bl2);
    cudaGetSymbolAddress((void**)&Ah,  g_Ah);
    cudaGetSymbolAddress((void**)&Al,  g_Al);

    // Pre-pass: transpose+split weights, split activations
    wsplitT<<<dim3(NQKV/32, NX/32), 256>>>(w_attn, Bh1, Bl1, NX, NQKV);
    wsplitT<<<dim3(NX/32,   NX/32), 256>>>(w_proj, Bh2, Bl2, NX, NX);
    asplit<<<(MROWS*NX)/(256*4), 256>>>(hidden, Ah, Al);

    // 1) QKV = X @ W_attn + b -> bf16 hi/lo Q/K/V, quirky per-head layout
    mma_gemm_impl<<<dim3(NQKV/128, MROWS/128), 256>>>(
        Ah, Al, Bh1, Bl1, b_attn, nullptr, NQKV, NX, 1);

    // 2) HMMA flash attention -> bf16 hi/lo activations
    attn_mma<<<dim3(SEQ/128, NH, BSZ), 256, ATTN_SMEM>>>(amask);

    // 3) out = A @ W_proj + b
    mma_gemm_impl<<<dim3(NX/128, MROWS/128), 256>>>(
        Ah, Al, Bh2, Bl2, b_proj, out, NX, NX, 0);
}

// round 11
// speedup vs baseline: 2.8277x; 1.0782x over previous
#include <cuda_runtime.h>
#include <cuda_bf16.h>
#include <math.h>
#include <stdint.h>

#define BSZ 2
#define SEQ 2048
#define NX 768
#define NH 12
#define HD 64
#define MROWS (BSZ*SEQ)      // 4096
#define NQKV (3*NX)          // 2304

// Scratch (no cudaMalloc allowed)
__device__ __nv_bfloat16 g_Qh[BSZ*NH*SEQ*HD];
__device__ __nv_bfloat16 g_Ql[BSZ*NH*SEQ*HD];
__device__ __nv_bfloat16 g_Kh[BSZ*NH*SEQ*HD];
__device__ __nv_bfloat16 g_Kl[BSZ*NH*SEQ*HD];
__device__ __nv_bfloat16 g_Vh[BSZ*NH*SEQ*HD];
__device__ __nv_bfloat16 g_Vl[BSZ*NH*SEQ*HD];
__device__ __nv_bfloat16 g_Ah[BSZ*SEQ*NX];   // attn out hi (feeds proj)
__device__ __nv_bfloat16 g_Al[BSZ*SEQ*NX];   // attn out lo
__device__ __nv_bfloat16 g_Bh1[NQKV*NX];     // w_attn^T hi  [2304][768]
__device__ __nv_bfloat16 g_Bl1[NQKV*NX];
__device__ __nv_bfloat16 g_Bh2[NX*NX];       // w_proj^T hi  [768][768]
__device__ __nv_bfloat16 g_Bl2[NX*NX];

// ---------------------------------------------------------------------------
// helpers
// ---------------------------------------------------------------------------
__device__ __forceinline__ uint32_t smem_u32(const void* p) {
    uint32_t a;
    asm("{ .reg .u64 t; cvta.to.shared.u64 t, %1; cvt.u32.u64 %0, t; }"
        : "=r"(a) : "l"(p));
    return a;
}
__device__ __forceinline__ void mma_bf16(float* d, const uint32_t* a, const uint32_t* b) {
    asm volatile(
        "mma.sync.aligned.m16n8k16.row.col.f32.bf16.bf16.f32 "
        "{%0,%1,%2,%3}, {%4,%5,%6,%7}, {%8,%9}, {%0,%1,%2,%3};"
        : "+f"(d[0]), "+f"(d[1]), "+f"(d[2]), "+f"(d[3])
        : "r"(a[0]), "r"(a[1]), "r"(a[2]), "r"(a[3]), "r"(b[0]), "r"(b[1]));
}
__device__ __forceinline__ void ldm_x4(uint32_t* r, uint32_t addr) {
    asm volatile("ldmatrix.sync.aligned.m8n8.x4.shared.b16 {%0,%1,%2,%3}, [%4];"
                 : "=r"(r[0]), "=r"(r[1]), "=r"(r[2]), "=r"(r[3]) : "r"(addr));
}
__device__ __forceinline__ void ldm_x2(uint32_t* r, uint32_t addr) {
    asm volatile("ldmatrix.sync.aligned.m8n8.x2.shared.b16 {%0,%1}, [%2];"
                 : "=r"(r[0]), "=r"(r[1]) : "r"(addr));
}
__device__ __forceinline__ void ldm_x4t(uint32_t* r, uint32_t addr) {
    asm volatile("ldmatrix.sync.aligned.m8n8.x4.trans.shared.b16 {%0,%1,%2,%3}, [%4];"
                 : "=r"(r[0]), "=r"(r[1]), "=r"(r[2]), "=r"(r[3]) : "r"(addr));
}
__device__ __forceinline__ void cp_async16(uint32_t dst, const void* src) {
    asm volatile("cp.async.cg.shared.global [%0], [%1], 16;"
                 :: "r"(dst), "l"(src) : "memory");
}
__device__ __forceinline__ void cp_commit() {
    asm volatile("cp.async.commit_group;" ::: "memory");
}
__device__ __forceinline__ void cp_wait0() {
    asm volatile("cp.async.wait_group 0;" ::: "memory");
}
// split two fp32 into packed bf16 hi2 / lo2
__device__ __forceinline__ void split2(float a, float b, uint32_t& hi, uint32_t& lo) {
    __nv_bfloat16 ha = __float2bfloat16_rn(a), hb = __float2bfloat16_rn(b);
    __nv_bfloat16 la = __float2bfloat16_rn(a - __bfloat162float(ha));
    __nv_bfloat16 lb = __float2bfloat16_rn(b - __bfloat162float(hb));
    __nv_bfloat162 H(ha, hb), L(la, lb);
    hi = *(uint32_t*)&H; lo = *(uint32_t*)&L;
}

// ---------------------------------------------------------------------------
// Pre-pass 1: transpose + bf16-split weights.  B[K,N] fp32 -> Th/Tl [N][K]
// ---------------------------------------------------------------------------
__global__ void __launch_bounds__(256)
wsplitT(const float* __restrict__ B, __nv_bfloat16* __restrict__ Th,
        __nv_bfloat16* __restrict__ Tl, int K, int N)
{
    __shared__ float t[32][33];
    const int c  = threadIdx.x & 31;
    const int r4 = threadIdx.x >> 5;
    const int n0 = blockIdx.x * 32;
    const int k0 = blockIdx.y * 32;
#pragma unroll
    for (int i = 0; i < 4; i++)
        t[r4 + 8*i][c] = B[(size_t)(k0 + r4 + 8*i) * N + n0 + c];
    __syncthreads();
#pragma unroll
    for (int i = 0; i < 4; i++) {
        const int n = n0 + r4 + 8*i;
        const float v = t[c][r4 + 8*i];
        const __nv_bfloat16 hi = __float2bfloat16_rn(v);
        Th[(size_t)n * K + k0 + c] = hi;
        Tl[(size_t)n * K + k0 + c] = __float2bfloat16_rn(v - __bfloat162float(hi));
    }
}

// Pre-pass 2: elementwise bf16 split of activations
__global__ void __launch_bounds__(256)
asplit(const float* __restrict__ X, __nv_bfloat16* __restrict__ H,
       __nv_bfloat16* __restrict__ L)
{
    const size_t i = (size_t)blockIdx.x * 256 + threadIdx.x;
    float4 x = ((const float4*)X)[i];
    uint32_t h0, l0, h1, l1;
    split2(x.x, x.y, h0, l0);
    split2(x.z, x.w, h1, l1);
    ((uint32_t*)H)[2*i]   = h0;
    ((uint32_t*)H)[2*i+1] = h1;
    ((uint32_t*)L)[2*i]   = l0;
    ((uint32_t*)L)[2*i+1] = l1;
}

// ---------------------------------------------------------------------------
// HMMA bf16 3-product GEMM: C = A @ Bt^T + bias
// cp.async 2-stage pipeline, 2 CTAs/SM (reg cap 128).  (unchanged from R10)
// MODE 1: writes Q/K/V bf16 hi/lo via the reference's QUIRKY direct reshape:
//         flat f = sq*768 + nn -> t = sq*NH + (nn>>6); h = t>>11; s2 = t&2047.
// MODE 0: fp32 C.
// ---------------------------------------------------------------------------
#define RP 24
#define GBUF (128*RP*2)      // bytes per buffer per array
__global__ void __launch_bounds__(256, 2)
mma_gemm_impl(const __nv_bfloat16* __restrict__ Ahg, const __nv_bfloat16* __restrict__ Alg,
              const __nv_bfloat16* __restrict__ Bhg, const __nv_bfloat16* __restrict__ Blg,
              const float* __restrict__ bias, float* __restrict__ C,
              int N, int K, int MODE)
{
    __shared__ __nv_bfloat16 sAh[2][128*RP];
    __shared__ __nv_bfloat16 sAl[2][128*RP];
    __shared__ __nv_bfloat16 sBh[2][128*RP];
    __shared__ __nv_bfloat16 sBl[2][128*RP];

    const int tid  = threadIdx.x;
    const int wid  = tid >> 5;
    const int lane = tid & 31;
    const int wm   = wid >> 2;
    const int wn   = wid & 3;
    const int m0 = blockIdx.y * 128;
    const int n0 = blockIdx.x * 128;

    const int row  = tid >> 1;
    const int half = tid & 1;
    const __nv_bfloat16* pAh = Ahg + (size_t)(m0 + row) * K + half * 8;
    const __nv_bfloat16* pAl = Alg + (size_t)(m0 + row) * K + half * 8;
    const __nv_bfloat16* pBh = Bhg + (size_t)(n0 + row) * K + half * 8;
    const __nv_bfloat16* pBl = Blg + (size_t)(n0 + row) * K + half * 8;
    const uint32_t sdb = (uint32_t)((row * RP + half * 8) * 2);   // byte offset

    const uint32_t bAh = smem_u32(sAh), bAl = smem_u32(sAl);
    const uint32_t bBh = smem_u32(sBh), bBl = smem_u32(sBl);
    uint32_t a_off[4], b_off[4];
    {
        const int ar = lane & 15, ak = (lane >> 4) * 16;
        const int bn = lane & 7,  bk = ((lane >> 3) & 1) * 16;
#pragma unroll
        for (int i = 0; i < 4; i++) a_off[i] = (uint32_t)((wm*64 + i*16 + ar) * (RP*2) + ak);
#pragma unroll
        for (int j = 0; j < 4; j++) b_off[j] = (uint32_t)((wn*32 + j*8 + bn) * (RP*2) + bk);
    }

    float acc[4][4][4];
#pragma unroll
    for (int i = 0; i < 4; i++)
#pragma unroll
        for (int j = 0; j < 4; j++)
#pragma unroll
            for (int t = 0; t < 4; t++) acc[i][j][t] = 0.0f;

    const int NC = K >> 4;

    // prologue: chunk 0 -> buf 0
    {
        cp_async16(bAh + sdb, pAh);
        cp_async16(bAl + sdb, pAl);
        cp_async16(bBh + sdb, pBh);
        cp_async16(bBl + sdb, pBl);
        cp_commit();
    }

    for (int kc = 0; kc < NC; kc++) {
        const int buf = kc & 1;
        const uint32_t bo = (uint32_t)buf * GBUF;
        cp_wait0();
        __syncthreads();                    // chunk kc visible; buf^1 reads done
        if (kc + 1 < NC) {
            const int ko = (kc + 1) * 16;
            const uint32_t dq = (uint32_t)(buf ^ 1) * GBUF + sdb;
            cp_async16(bAh + dq, pAh + ko);
            cp_async16(bAl + dq, pAl + ko);
            cp_async16(bBh + dq, pBh + ko);
            cp_async16(bBl + dq, pBl + ko);
            cp_commit();
        }

        uint32_t fbh[4][2], fbl[4][2];
#pragma unroll
        for (int j = 0; j < 4; j++) {
            ldm_x2(fbh[j], bBh + bo + b_off[j]);
            ldm_x2(fbl[j], bBl + bo + b_off[j]);
        }
#pragma unroll
        for (int i = 0; i < 4; i++) {
            uint32_t fah[4], fal[4];
            ldm_x4(fah, bAh + bo + a_off[i]);
            ldm_x4(fal, bAl + bo + a_off[i]);
#pragma unroll
            for (int j = 0; j < 4; j++) {
                mma_bf16(acc[i][j], fah, fbh[j]);
                mma_bf16(acc[i][j], fah, fbl[j]);
                mma_bf16(acc[i][j], fal, fbh[j]);
            }
        }
    }

    const int lr = lane >> 2;
    const int lc = (lane & 3) << 1;
#pragma unroll
    for (int i = 0; i < 4; i++) {
        const int m = m0 + wm*64 + i*16 + lr;
#pragma unroll
        for (int j = 0; j < 4; j++) {
            const int n = n0 + wn*32 + j*8 + lc;
            const float b0 = bias[n], b1 = bias[n + 1];
            const float v00 = acc[i][j][0] + b0, v01 = acc[i][j][1] + b1;
            const float v10 = acc[i][j][2] + b0, v11 = acc[i][j][3] + b1;
            if (MODE == 0) {
                *(float2*)(C + (size_t)m * N + n) = make_float2(v00, v01);
                *(float2*)(C + (size_t)(m + 8) * N + n) = make_float2(v10, v11);
            } else {
                const int sect = n0 / NX;            // 0=Q,1=K,2=V
                const int nn = n - sect * NX;
                const int d  = nn & 63;
                const int b  = m >> 11;
                const int sq = m & (SEQ - 1);
                __nv_bfloat16* Hd = (sect == 0) ? g_Qh : (sect == 1) ? g_Kh : g_Vh;
                __nv_bfloat16* Ld = (sect == 0) ? g_Ql : (sect == 1) ? g_Kl : g_Vl;
                // Quirky direct reshape: t = sq*NH + nn/64 -> (h, s2)
                const int t0 = sq * NH + (nn >> 6);
                const int h0 = t0 >> 11, s20 = t0 & (SEQ - 1);
                const int t1 = (sq + 8) * NH + (nn >> 6);     // row m+8, same b
                const int h1 = t1 >> 11, s21 = t1 & (SEQ - 1);
                const size_t base0 = ((size_t)(b*NH + h0) * SEQ + s20) * HD + d;
                const size_t base1 = ((size_t)(b*NH + h1) * SEQ + s21) * HD + d;
                uint32_t hi0, lo0, hi1, lo1;
                split2(v00, v01, hi0, lo0);
                split2(v10, v11, hi1, lo1);
                *(uint32_t*)(Hd + base0) = hi0;
                *(uint32_t*)(Ld + base0) = lo0;
                *(uint32_t*)(Hd + base1) = hi1;
                *(uint32_t*)(Ld + base1) = lo1;
            }
        }
    }
}

// ---------------------------------------------------------------------------
// HMMA flash attention: q-tile 128, k-tile 64, 8 warps x 16 q-rows.
// R11: Q hi/lo resides in SMEM (loaded once) -> -64 regs -> 2 CTAs/SM
// (reg cap 128).  ldmatrix merged to x4 (K: 2 j's/load, V: 2 dn's/load).
// smem: Q 36 KB + K/V double-buffered 72 KB = 110.6 KB -> 2 CTAs/SM.
// ---------------------------------------------------------------------------
#define ARP 72
#define ARPB (ARP*2)
#define QTILEB (128*ARPB)           // 18432 B per Q array
#define ATILE (64*ARPB)             // 9216 B per K/V array per buffer
#define ASTRIDE (2*ATILE)
#define ATTN_SMEM (2*QTILEB + 4*ASTRIDE)   // 110592 B

__global__ void __launch_bounds__(256, 2)
attn_mma(const float* __restrict__ amask)
{
    extern __shared__ __nv_bfloat16 dynsm[];

    const int tid  = threadIdx.x;
    const int wid  = tid >> 5;
    const int lane = tid & 31;
    const int qb = gridDim.x - 1 - blockIdx.x;   // long CTAs first
    const int h  = blockIdx.y;
    const int b  = blockIdx.z;
    const int q0 = qb * 128;
    const int qw = q0 + wid * 16;                // warp's 16 q-rows

    const size_t hoff = (size_t)(b*NH + h) * SEQ * HD;
    const __nv_bfloat16* Qg = g_Qh + hoff;
    const __nv_bfloat16* Qlg = g_Ql + hoff;
    const __nv_bfloat16* Kh = g_Kh + hoff;
    const __nv_bfloat16* Kl = g_Kl + hoff;
    const __nv_bfloat16* Vh = g_Vh + hoff;
    const __nv_bfloat16* Vl = g_Vl + hoff;
    const float* am = amask + (size_t)b * SEQ;

    const int r  = lane >> 2;          // 0..7
    const int c2 = (lane & 3) << 1;    // 0,2,4,6

    const uint32_t sm0 = smem_u32(dynsm);
    const uint32_t bQh = sm0;
    const uint32_t bQl = sm0 + QTILEB;
    const uint32_t kvb = sm0 + 2*QTILEB;
    const uint32_t bKh = kvb;
    const uint32_t bKl = kvb + ASTRIDE;
    const uint32_t bVh = kvb + 2*ASTRIDE;
    const uint32_t bVl = kvb + 3*ASTRIDE;

    // lane addresses
    // Q A-frag (x4): same formula as GEMM A (verified): rows qw_local + lane&15,
    // col bytes (lane>>4)*16, + ds*32 per 16-k step.
    const uint32_t qa_off = (uint32_t)((wid*16 + (lane & 15)) * ARPB + (lane >> 4) * 16);
    // K B-frag x4 (2 j's per load): matrices {j, j+1} x k-halves
    uint32_t kb4_off[4];
#pragma unroll
    for (int jp = 0; jp < 4; jp++)
        kb4_off[jp] = (uint32_t)((jp*16 + (lane >> 4)*8 + (lane & 7)) * ARPB
                                 + ((lane >> 3) & 1) * 16);
    // V B-frag x4.trans (2 dn's per load): rows lane&15, col dn via lane>>4
    const uint32_t vt4 = (uint32_t)((lane & 15) * ARPB + (lane >> 4) * 16);

    float acc[8][4];
#pragma unroll
    for (int j = 0; j < 8; j++)
#pragma unroll
        for (int t = 0; t < 4; t++) acc[j][t] = 0.0f;
    float mrow0 = -3.0e38f, mrow1 = -3.0e38f, lrow0 = 0.0f, lrow1 = 0.0f;

    // K/V tile loaders: full 64x64, 2 x 16B per thread per array
    const int trow = tid >> 3;
    const int tcol = (tid & 7) << 3;
    const uint32_t tdst = (uint32_t)(trow * ARPB + tcol * 2);

    const int nkb = 2 * qb + 2;
    const int qr0 = qw + r, qr1 = qw + r + 8;

    // prologue: Q tile (once) + K/V tile 0 -> buf 0
    {
        const int qrow = tid >> 1;
        const int qcb  = (tid & 1) * 32;           // elems
        const uint32_t qd = (uint32_t)(qrow * ARPB + qcb * 2);
        const size_t qs = (size_t)(q0 + qrow) * HD + qcb;
#pragma unroll
        for (int c = 0; c < 4; c++) {
            cp_async16(bQh + qd + c*16, Qg  + qs + c*8);
            cp_async16(bQl + qd + c*16, Qlg + qs + c*8);
        }
#pragma unroll
        for (int it = 0; it < 2; it++) {
            const int rr = trow + it * 32;
            const size_t src = (size_t)rr * HD + tcol;
            const uint32_t dst = tdst + (uint32_t)(it * 32 * ARPB);
            cp_async16(bKh + dst, Kh + src);
            cp_async16(bKl + dst, Kl + src);
            cp_async16(bVh + dst, Vh + src);
            cp_async16(bVl + dst, Vl + src);
        }
        cp_commit();
    }

    for (int kb = 0; kb < nkb; kb++) {
        const int k0 = kb * 64;
        const uint32_t bo = (uint32_t)(kb & 1) * ATILE;
        cp_wait0();
        __syncthreads();                 // tile kb (and Q on kb=0) visible
        if (kb + 1 < nkb) {
            const int kn = k0 + 64;
            const uint32_t bq = (uint32_t)((kb + 1) & 1) * ATILE;
#pragma unroll
            for (int it = 0; it < 2; it++) {
                const int rr = trow + it * 32;
                const size_t src = (size_t)(kn + rr) * HD + tcol;
                const uint32_t dst = bq + tdst + (uint32_t)(it * 32 * ARPB);
                cp_async16(bKh + dst, Kh + src);
                cp_async16(bKl + dst, Kl + src);
                cp_async16(bVh + dst, Vh + src);
                cp_async16(bVl + dst, Vl + src);
            }
            cp_commit();
        }

        // S = Q @ K^T (3-product), Q frags from smem
        float s[8][4];
#pragma unroll
        for (int j = 0; j < 8; j++)
#pragma unroll
            for (int t = 0; t < 4; t++) s[j][t] = 0.0f;
#pragma unroll
        for (int ds = 0; ds < 4; ds++) {
            uint32_t fqh[4], fql[4];
            ldm_x4(fqh, bQh + qa_off + ds * 32);
            ldm_x4(fql, bQl + qa_off + ds * 32);
#pragma unroll
            for (int jp = 0; jp < 4; jp++) {
                uint32_t fkh[4], fkl[4];
                ldm_x4(fkh, bKh + bo + kb4_off[jp] + ds * 32);
                ldm_x4(fkl, bKl + bo + kb4_off[jp] + ds * 32);
                mma_bf16(s[2*jp],   fqh, fkh + 0);
                mma_bf16(s[2*jp],   fqh, fkl + 0);
                mma_bf16(s[2*jp],   fql, fkh + 0);
                mma_bf16(s[2*jp+1], fqh, fkh + 2);
                mma_bf16(s[2*jp+1], fqh, fkl + 2);
                mma_bf16(s[2*jp+1], fql, fkh + 2);
            }
        }

        // mask + online softmax (rows qr0, qr1)
        float rmax0 = -3.0e38f, rmax1 = -3.0e38f;
#pragma unroll
        for (int j = 0; j < 8; j++) {
            const int k = k0 + j*8 + c2;
            const float2 amv = *(const float2*)(am + k);
            s[j][0] = (k   <= qr0) ? s[j][0]*0.125f + amv.x : -10000.0f + amv.x;
            s[j][1] = (k+1 <= qr0) ? s[j][1]*0.125f + amv.y : -10000.0f + amv.y;
            s[j][2] = (k   <= qr1) ? s[j][2]*0.125f + amv.x : -10000.0f + amv.x;
            s[j][3] = (k+1 <= qr1) ? s[j][3]*0.125f + amv.y : -10000.0f + amv.y;
            rmax0 = fmaxf(rmax0, fmaxf(s[j][0], s[j][1]));
            rmax1 = fmaxf(rmax1, fmaxf(s[j][2], s[j][3]));
        }
        rmax0 = fmaxf(rmax0, __shfl_xor_sync(0xffffffffu, rmax0, 1));
        rmax0 = fmaxf(rmax0, __shfl_xor_sync(0xffffffffu, rmax0, 2));
        rmax1 = fmaxf(rmax1, __shfl_xor_sync(0xffffffffu, rmax1, 1));
        rmax1 = fmaxf(rmax1, __shfl_xor_sync(0xffffffffu, rmax1, 2));
        const float mnew0 = fmaxf(mrow0, rmax0);
        const float mnew1 = fmaxf(mrow1, rmax1);
        const float corr0 = __expf(mrow0 - mnew0);
        const float corr1 = __expf(mrow1 - mnew1);
        float rsum0 = 0.0f, rsum1 = 0.0f;
#pragma unroll
        for (int j = 0; j < 8; j++) {
            s[j][0] = __expf(s[j][0] - mnew0);
            s[j][1] = __expf(s[j][1] - mnew0);
            s[j][2] = __expf(s[j][2] - mnew1);
            s[j][3] = __expf(s[j][3] - mnew1);
            rsum0 += s[j][0] + s[j][1];
            rsum1 += s[j][2] + s[j][3];
        }
        rsum0 += __shfl_xor_sync(0xffffffffu, rsum0, 1);
        rsum0 += __shfl_xor_sync(0xffffffffu, rsum0, 2);
        rsum1 += __shfl_xor_sync(0xffffffffu, rsum1, 1);
        rsum1 += __shfl_xor_sync(0xffffffffu, rsum1, 2);
        lrow0 = lrow0 * corr0 + rsum0;
        lrow1 = lrow1 * corr1 + rsum1;
        mrow0 = mnew0; mrow1 = mnew1;
#pragma unroll
        for (int j = 0; j < 8; j++) {
            acc[j][0] *= corr0; acc[j][1] *= corr0;
            acc[j][2] *= corr1; acc[j][3] *= corr1;
        }

        // P fragments (register repack: A-frag t from S n-frags 2t, 2t+1)
        uint32_t fph[4][4], fpl[4][4];
#pragma unroll
        for (int t = 0; t < 4; t++) {
            split2(s[2*t][0],   s[2*t][1],   fph[t][0], fpl[t][0]);
            split2(s[2*t][2],   s[2*t][3],   fph[t][1], fpl[t][1]);
            split2(s[2*t+1][0], s[2*t+1][1], fph[t][2], fpl[t][2]);
            split2(s[2*t+1][2], s[2*t+1][3], fph[t][3], fpl[t][3]);
        }

        // O += P @ V (3-product; V x4.trans: 2 dn's per load)
#pragma unroll
        for (int t = 0; t < 4; t++) {
            const uint32_t ro = bo + vt4 + (uint32_t)(t * 16 * ARPB);
#pragma unroll
            for (int dnp = 0; dnp < 4; dnp++) {
                uint32_t fvh[4], fvl[4];
                ldm_x4t(fvh, bVh + ro + dnp * 32);
                ldm_x4t(fvl, bVl + ro + dnp * 32);
                mma_bf16(acc[2*dnp],   fph[t], fvh + 0);
                mma_bf16(acc[2*dnp],   fph[t], fvl + 0);
                mma_bf16(acc[2*dnp],   fpl[t], fvh + 0);
                mma_bf16(acc[2*dnp+1], fph[t], fvh + 2);
                mma_bf16(acc[2*dnp+1], fph[t], fvl + 2);
                mma_bf16(acc[2*dnp+1], fpl[t], fvh + 2);
            }
        }
    }

    // epilogue: normalize, bf16 hi/lo split into g_Ah/g_Al at [b, q_view, h*64+d]
    const float inv0 = 1.0f / lrow0;
    const float inv1 = 1.0f / lrow1;
#pragma unroll
    for (int dn = 0; dn < 8; dn++) {
        const int d = dn*8 + c2;
        uint32_t hi0, lo0, hi1, lo1;
        split2(acc[dn][0]*inv0, acc[dn][1]*inv0, hi0, lo0);
        split2(acc[dn][2]*inv1, acc[dn][3]*inv1, hi1, lo1);
        const size_t i0 = ((size_t)b * SEQ + qr0) * NX + h * HD + d;
        const size_t i1 = ((size_t)b * SEQ + qr1) * NX + h * HD + d;
        *(uint32_t*)(g_Ah + i0) = hi0;
        *(uint32_t*)(g_Al + i0) = lo0;
        *(uint32_t*)(g_Ah + i1) = hi1;
        *(uint32_t*)(g_Al + i1) = lo1;
    }
}

// ---------------------------------------------------------------------------
extern "C" void kernel_launch(void* const* d_in, const int* in_sizes, int n_in,
                              void* d_out, int out_size)
{
    const float* hidden = (const float*)d_in[0];
    const float* amask  = (const float*)d_in[1];
    const float* w_attn = (const float*)d_in[2];
    const float* b_attn = (const float*)d_in[3];
    const float* w_proj = (const float*)d_in[4];
    const float* b_proj = (const float*)d_in[5];
    float* out = (float*)d_out;

    // Host-side attribute set: not a stream op, graph-capture-safe, idempotent.
    cudaFuncSetAttribute(attn_mma, cudaFuncAttributeMaxDynamicSharedMemorySize,
                         ATTN_SMEM);

    __nv_bfloat16 *Bh1, *Bl1, *Bh2, *Bl2, *Ah, *Al;
    cudaGetSymbolAddress((void**)&Bh1, g_Bh1);
    cudaGetSymbolAddress((void**)&Bl1, g_Bl1);
    cudaGetSymbolAddress((void**)&Bh2, g_Bh2);
    cudaGetSymbolAddress((void**)&Bl2, g_Bl2);
    cudaGetSymbolAddress((void**)&Ah,  g_Ah);
    cudaGetSymbolAddress((void**)&Al,  g_Al);

    // Pre-pass: transpose+split weights, split activations
    wsplitT<<<dim3(NQKV/32, NX/32), 256>>>(w_attn, Bh1, Bl1, NX, NQKV);
    wsplitT<<<dim3(NX/32,   NX/32), 256>>>(w_proj, Bh2, Bl2, NX, NX);
    asplit<<<(MROWS*NX)/(256*4), 256>>>(hidden, Ah, Al);

    // 1) QKV = X @ W_attn + b -> bf16 hi/lo Q/K/V, quirky per-head layout
    mma_gemm_impl<<<dim3(NQKV/128, MROWS/128), 256>>>(
        Ah, Al, Bh1, Bl1, b_attn, nullptr, NQKV, NX, 1);

    // 2) HMMA flash attention -> bf16 hi/lo activations
    attn_mma<<<dim3(SEQ/128, NH, BSZ), 256, ATTN_SMEM>>>(amask);

    // 3) out = A @ W_proj + b
    mma_gemm_impl<<<dim3(NX/128, MROWS/128), 256>>>(
        Ah, Al, Bh2, Bl2, b_proj, out, NX, NX, 0);
}

// round 13
// speedup vs baseline: 2.8864x; 1.0208x over previous
#include <cuda_runtime.h>
#include <cuda_bf16.h>
#include <math.h>
#include <stdint.h>

#define BSZ 2
#define SEQ 2048
#define NX 768
#define NH 12
#define HD 64
#define MROWS (BSZ*SEQ)      // 4096
#define NQKV (3*NX)          // 2304

// Scratch (no cudaMalloc allowed)
__device__ __nv_bfloat16 g_Qh[BSZ*NH*SEQ*HD];
__device__ __nv_bfloat16 g_Ql[BSZ*NH*SEQ*HD];
__device__ __nv_bfloat16 g_Kh[BSZ*NH*SEQ*HD];
__device__ __nv_bfloat16 g_Kl[BSZ*NH*SEQ*HD];
__device__ __nv_bfloat16 g_Vh[BSZ*NH*SEQ*HD];
__device__ __nv_bfloat16 g_Vl[BSZ*NH*SEQ*HD];
__device__ __nv_bfloat16 g_Ah[BSZ*SEQ*NX];   // attn out hi (feeds proj)
__device__ __nv_bfloat16 g_Al[BSZ*SEQ*NX];   // attn out lo
__device__ __nv_bfloat16 g_Bh1[NQKV*NX];     // w_attn^T hi  [2304][768]
__device__ __nv_bfloat16 g_Bl1[NQKV*NX];
__device__ __nv_bfloat16 g_Bh2[NX*NX];       // w_proj^T hi  [768][768]
__device__ __nv_bfloat16 g_Bl2[NX*NX];

// ---------------------------------------------------------------------------
// helpers
// ---------------------------------------------------------------------------
__device__ __forceinline__ uint32_t smem_u32(const void* p) {
    uint32_t a;
    asm("{ .reg .u64 t; cvta.to.shared.u64 t, %1; cvt.u32.u64 %0, t; }"
        : "=r"(a) : "l"(p));
    return a;
}
__device__ __forceinline__ void mma_bf16(float* d, const uint32_t* a, const uint32_t* b) {
    asm volatile(
        "mma.sync.aligned.m16n8k16.row.col.f32.bf16.bf16.f32 "
        "{%0,%1,%2,%3}, {%4,%5,%6,%7}, {%8,%9}, {%0,%1,%2,%3};"
        : "+f"(d[0]), "+f"(d[1]), "+f"(d[2]), "+f"(d[3])
        : "r"(a[0]), "r"(a[1]), "r"(a[2]), "r"(a[3]), "r"(b[0]), "r"(b[1]));
}
__device__ __forceinline__ void ldm_x4(uint32_t* r, uint32_t addr) {
    asm volatile("ldmatrix.sync.aligned.m8n8.x4.shared.b16 {%0,%1,%2,%3}, [%4];"
                 : "=r"(r[0]), "=r"(r[1]), "=r"(r[2]), "=r"(r[3]) : "r"(addr));
}
__device__ __forceinline__ void ldm_x2(uint32_t* r, uint32_t addr) {
    asm volatile("ldmatrix.sync.aligned.m8n8.x2.shared.b16 {%0,%1}, [%2];"
                 : "=r"(r[0]), "=r"(r[1]) : "r"(addr));
}
__device__ __forceinline__ void ldm_x4t(uint32_t* r, uint32_t addr) {
    asm volatile("ldmatrix.sync.aligned.m8n8.x4.trans.shared.b16 {%0,%1,%2,%3}, [%4];"
                 : "=r"(r[0]), "=r"(r[1]), "=r"(r[2]), "=r"(r[3]) : "r"(addr));
}
__device__ __forceinline__ void cp_async16(uint32_t dst, const void* src) {
    asm volatile("cp.async.cg.shared.global [%0], [%1], 16;"
                 :: "r"(dst), "l"(src) : "memory");
}
__device__ __forceinline__ void cp_commit() {
    asm volatile("cp.async.commit_group;" ::: "memory");
}
__device__ __forceinline__ void cp_wait0() {
    asm volatile("cp.async.wait_group 0;" ::: "memory");
}
// split two fp32 into packed bf16 hi2 / lo2
__device__ __forceinline__ void split2(float a, float b, uint32_t& hi, uint32_t& lo) {
    __nv_bfloat16 ha = __float2bfloat16_rn(a), hb = __float2bfloat16_rn(b);
    __nv_bfloat16 la = __float2bfloat16_rn(a - __bfloat162float(ha));
    __nv_bfloat16 lb = __float2bfloat16_rn(b - __bfloat162float(hb));
    __nv_bfloat162 H(ha, hb), L(la, lb);
    hi = *(uint32_t*)&H; lo = *(uint32_t*)&L;
}

// ---------------------------------------------------------------------------
// Pre-pass 1: transpose + bf16-split weights.  B[K,N] fp32 -> Th/Tl [N][K]
// ---------------------------------------------------------------------------
__global__ void __launch_bounds__(256)
wsplitT(const float* __restrict__ B, __nv_bfloat16* __restrict__ Th,
        __nv_bfloat16* __restrict__ Tl, int K, int N)
{
    __shared__ float t[32][33];
    const int c  = threadIdx.x & 31;
    const int r4 = threadIdx.x >> 5;
    const int n0 = blockIdx.x * 32;
    const int k0 = blockIdx.y * 32;
#pragma unroll
    for (int i = 0; i < 4; i++)
        t[r4 + 8*i][c] = B[(size_t)(k0 + r4 + 8*i) * N + n0 + c];
    __syncthreads();
#pragma unroll
    for (int i = 0; i < 4; i++) {
        const int n = n0 + r4 + 8*i;
        const float v = t[c][r4 + 8*i];
        const __nv_bfloat16 hi = __float2bfloat16_rn(v);
        Th[(size_t)n * K + k0 + c] = hi;
        Tl[(size_t)n * K + k0 + c] = __float2bfloat16_rn(v - __bfloat162float(hi));
    }
}

// Pre-pass 2: elementwise bf16 split of activations
__global__ void __launch_bounds__(256)
asplit(const float* __restrict__ X, __nv_bfloat16* __restrict__ H,
       __nv_bfloat16* __restrict__ L)
{
    const size_t i = (size_t)blockIdx.x * 256 + threadIdx.x;
    float4 x = ((const float4*)X)[i];
    uint32_t h0, l0, h1, l1;
    split2(x.x, x.y, h0, l0);
    split2(x.z, x.w, h1, l1);
    ((uint32_t*)H)[2*i]   = h0;
    ((uint32_t*)H)[2*i+1] = h1;
    ((uint32_t*)L)[2*i]   = l0;
    ((uint32_t*)L)[2*i+1] = l1;
}

// ---------------------------------------------------------------------------
// HMMA bf16 3-product GEMM: C = A @ Bt^T + bias
// cp.async 2-stage pipeline, 2 CTAs/SM (reg cap 128).
// R12: MMA emission reordered so consecutive MMAs hit DIFFERENT accumulators
// (RAW distance 4 instead of 1) — asm volatile pins program order, so the
// source order IS the issue order.
// MODE 1: writes Q/K/V bf16 hi/lo via the reference's QUIRKY direct reshape:
//         flat f = sq*768 + nn -> t = sq*NH + (nn>>6); h = t>>11; s2 = t&2047.
// MODE 0: fp32 C.
// ---------------------------------------------------------------------------
#define RP 24
#define GBUF (128*RP*2)      // bytes per buffer per array
__global__ void __launch_bounds__(256, 2)
mma_gemm_impl(const __nv_bfloat16* __restrict__ Ahg, const __nv_bfloat16* __restrict__ Alg,
              const __nv_bfloat16* __restrict__ Bhg, const __nv_bfloat16* __restrict__ Blg,
              const float* __restrict__ bias, float* __restrict__ C,
              int N, int K, int MODE)
{
    __shared__ __nv_bfloat16 sAh[2][128*RP];
    __shared__ __nv_bfloat16 sAl[2][128*RP];
    __shared__ __nv_bfloat16 sBh[2][128*RP];
    __shared__ __nv_bfloat16 sBl[2][128*RP];

    const int tid  = threadIdx.x;
    const int wid  = tid >> 5;
    const int lane = tid & 31;
    const int wm   = wid >> 2;
    const int wn   = wid & 3;
    const int m0 = blockIdx.y * 128;
    const int n0 = blockIdx.x * 128;

    const int row  = tid >> 1;
    const int half = tid & 1;
    const __nv_bfloat16* pAh = Ahg + (size_t)(m0 + row) * K + half * 8;
    const __nv_bfloat16* pAl = Alg + (size_t)(m0 + row) * K + half * 8;
    const __nv_bfloat16* pBh = Bhg + (size_t)(n0 + row) * K + half * 8;
    const __nv_bfloat16* pBl = Blg + (size_t)(n0 + row) * K + half * 8;
    const uint32_t sdb = (uint32_t)((row * RP + half * 8) * 2);   // byte offset

    const uint32_t bAh = smem_u32(sAh), bAl = smem_u32(sAl);
    const uint32_t bBh = smem_u32(sBh), bBl = smem_u32(sBl);
    uint32_t a_off[4], b_off[4];
    {
        const int ar = lane & 15, ak = (lane >> 4) * 16;
        const int bn = lane & 7,  bk = ((lane >> 3) & 1) * 16;
#pragma unroll
        for (int i = 0; i < 4; i++) a_off[i] = (uint32_t)((wm*64 + i*16 + ar) * (RP*2) + ak);
#pragma unroll
        for (int j = 0; j < 4; j++) b_off[j] = (uint32_t)((wn*32 + j*8 + bn) * (RP*2) + bk);
    }

    float acc[4][4][4];
#pragma unroll
    for (int i = 0; i < 4; i++)
#pragma unroll
        for (int j = 0; j < 4; j++)
#pragma unroll
            for (int t = 0; t < 4; t++) acc[i][j][t] = 0.0f;

    const int NC = K >> 4;

    // prologue: chunk 0 -> buf 0
    {
        cp_async16(bAh + sdb, pAh);
        cp_async16(bAl + sdb, pAl);
        cp_async16(bBh + sdb, pBh);
        cp_async16(bBl + sdb, pBl);
        cp_commit();
    }

    for (int kc = 0; kc < NC; kc++) {
        const int buf = kc & 1;
        const uint32_t bo = (uint32_t)buf * GBUF;
        cp_wait0();
        __syncthreads();                    // chunk kc visible; buf^1 reads done
        if (kc + 1 < NC) {
            const int ko = (kc + 1) * 16;
            const uint32_t dq = (uint32_t)(buf ^ 1) * GBUF + sdb;
            cp_async16(bAh + dq, pAh + ko);
            cp_async16(bAl + dq, pAl + ko);
            cp_async16(bBh + dq, pBh + ko);
            cp_async16(bBl + dq, pBl + ko);
            cp_commit();
        }

        uint32_t fbh[4][2], fbl[4][2];
#pragma unroll
        for (int j = 0; j < 4; j++) {
            ldm_x2(fbh[j], bBh + bo + b_off[j]);
            ldm_x2(fbl[j], bBl + bo + b_off[j]);
        }
#pragma unroll
        for (int i = 0; i < 4; i++) {
            uint32_t fah[4], fal[4];
            ldm_x4(fah, bAh + bo + a_off[i]);
            ldm_x4(fal, bAl + bo + a_off[i]);
            // RAW distance 4: sweep j per product
#pragma unroll
            for (int j = 0; j < 4; j++) mma_bf16(acc[i][j], fah, fbh[j]);
#pragma unroll
            for (int j = 0; j < 4; j++) mma_bf16(acc[i][j], fah, fbl[j]);
#pragma unroll
            for (int j = 0; j < 4; j++) mma_bf16(acc[i][j], fal, fbh[j]);
        }
    }

    const int lr = lane >> 2;
    const int lc = (lane & 3) << 1;
#pragma unroll
    for (int i = 0; i < 4; i++) {
        const int m = m0 + wm*64 + i*16 + lr;
#pragma unroll
        for (int j = 0; j < 4; j++) {
            const int n = n0 + wn*32 + j*8 + lc;
            const float b0 = bias[n], b1 = bias[n + 1];
            const float v00 = acc[i][j][0] + b0, v01 = acc[i][j][1] + b1;
            const float v10 = acc[i][j][2] + b0, v11 = acc[i][j][3] + b1;
            if (MODE == 0) {
                *(float2*)(C + (size_t)m * N + n) = make_float2(v00, v01);
                *(float2*)(C + (size_t)(m + 8) * N + n) = make_float2(v10, v11);
            } else {
                const int sect = n0 / NX;            // 0=Q,1=K,2=V
                const int nn = n - sect * NX;
                const int d  = nn & 63;
                const int b  = m >> 11;
                const int sq = m & (SEQ - 1);
                __nv_bfloat16* Hd = (sect == 0) ? g_Qh : (sect == 1) ? g_Kh : g_Vh;
                __nv_bfloat16* Ld = (sect == 0) ? g_Ql : (sect == 1) ? g_Kl : g_Vl;
                // Quirky direct reshape: t = sq*NH + nn/64 -> (h, s2)
                const int t0 = sq * NH + (nn >> 6);
                const int h0 = t0 >> 11, s20 = t0 & (SEQ - 1);
                const int t1 = (sq + 8) * NH + (nn >> 6);     // row m+8, same b
                const int h1 = t1 >> 11, s21 = t1 & (SEQ - 1);
                const size_t base0 = ((size_t)(b*NH + h0) * SEQ + s20) * HD + d;
                const size_t base1 = ((size_t)(b*NH + h1) * SEQ + s21) * HD + d;
                uint32_t hi0, lo0, hi1, lo1;
                split2(v00, v01, hi0, lo0);
                split2(v10, v11, hi1, lo1);
                *(uint32_t*)(Hd + base0) = hi0;
                *(uint32_t*)(Ld + base0) = lo0;
                *(uint32_t*)(Hd + base1) = hi1;
                *(uint32_t*)(Ld + base1) = lo1;
            }
        }
    }
}

// ---------------------------------------------------------------------------
// HMMA flash attention: q-tile 128, k-tile 64, 8 warps x 16 q-rows.
// Q hi/lo in SMEM, K/V cp.async double-buffered, 2 CTAs/SM.
// R12: MMA emission interleaved across the two accumulators of each pair
// (RAW distance 2 instead of 1) in both S and P@V phases.
// ---------------------------------------------------------------------------
#define ARP 72
#define ARPB (ARP*2)
#define QTILEB (128*ARPB)           // 18432 B per Q array
#define ATILE (64*ARPB)             // 9216 B per K/V array per buffer
#define ASTRIDE (2*ATILE)
#define ATTN_SMEM (2*QTILEB + 4*ASTRIDE)   // 110592 B

__global__ void __launch_bounds__(256, 2)
attn_mma(const float* __restrict__ amask)
{
    extern __shared__ __nv_bfloat16 dynsm[];

    const int tid  = threadIdx.x;
    const int wid  = tid >> 5;
    const int lane = tid & 31;
    const int qb = gridDim.x - 1 - blockIdx.x;   // long CTAs first
    const int h  = blockIdx.y;
    const int b  = blockIdx.z;
    const int q0 = qb * 128;
    const int qw = q0 + wid * 16;                // warp's 16 q-rows

    const size_t hoff = (size_t)(b*NH + h) * SEQ * HD;
    const __nv_bfloat16* Qg = g_Qh + hoff;
    const __nv_bfloat16* Qlg = g_Ql + hoff;
    const __nv_bfloat16* Kh = g_Kh + hoff;
    const __nv_bfloat16* Kl = g_Kl + hoff;
    const __nv_bfloat16* Vh = g_Vh + hoff;
    const __nv_bfloat16* Vl = g_Vl + hoff;
    const float* am = amask + (size_t)b * SEQ;

    const int r  = lane >> 2;          // 0..7
    const int c2 = (lane & 3) << 1;    // 0,2,4,6

    const uint32_t sm0 = smem_u32(dynsm);
    const uint32_t bQh = sm0;
    const uint32_t bQl = sm0 + QTILEB;
    const uint32_t kvb = sm0 + 2*QTILEB;
    const uint32_t bKh = kvb;
    const uint32_t bKl = kvb + ASTRIDE;
    const uint32_t bVh = kvb + 2*ASTRIDE;
    const uint32_t bVl = kvb + 3*ASTRIDE;

    // lane addresses
    const uint32_t qa_off = (uint32_t)((wid*16 + (lane & 15)) * ARPB + (lane >> 4) * 16);
    uint32_t kb4_off[4];
#pragma unroll
    for (int jp = 0; jp < 4; jp++)
        kb4_off[jp] = (uint32_t)((jp*16 + (lane >> 4)*8 + (lane & 7)) * ARPB
                                 + ((lane >> 3) & 1) * 16);
    const uint32_t vt4 = (uint32_t)((lane & 15) * ARPB + (lane >> 4) * 16);

    float acc[8][4];
#pragma unroll
    for (int j = 0; j < 8; j++)
#pragma unroll
        for (int t = 0; t < 4; t++) acc[j][t] = 0.0f;
    float mrow0 = -3.0e38f, mrow1 = -3.0e38f, lrow0 = 0.0f, lrow1 = 0.0f;

    // K/V tile loaders: full 64x64, 2 x 16B per thread per array
    const int trow = tid >> 3;
    const int tcol = (tid & 7) << 3;
    const uint32_t tdst = (uint32_t)(trow * ARPB + tcol * 2);

    const int nkb = 2 * qb + 2;
    const int qr0 = qw + r, qr1 = qw + r + 8;

    // prologue: Q tile (once) + K/V tile 0 -> buf 0
    {
        const int qrow = tid >> 1;
        const int qcb  = (tid & 1) * 32;           // elems
        const uint32_t qd = (uint32_t)(qrow * ARPB + qcb * 2);
        const size_t qs = (size_t)(q0 + qrow) * HD + qcb;
#pragma unroll
        for (int c = 0; c < 4; c++) {
            cp_async16(bQh + qd + c*16, Qg  + qs + c*8);
            cp_async16(bQl + qd + c*16, Qlg + qs + c*8);
        }
#pragma unroll
        for (int it = 0; it < 2; it++) {
            const int rr = trow + it * 32;
            const size_t src = (size_t)rr * HD + tcol;
            const uint32_t dst = tdst + (uint32_t)(it * 32 * ARPB);
            cp_async16(bKh + dst, Kh + src);
            cp_async16(bKl + dst, Kl + src);
            cp_async16(bVh + dst, Vh + src);
            cp_async16(bVl + dst, Vl + src);
        }
        cp_commit();
    }

    for (int kb = 0; kb < nkb; kb++) {
        const int k0 = kb * 64;
        const uint32_t bo = (uint32_t)(kb & 1) * ATILE;
        cp_wait0();
        __syncthreads();                 // tile kb (and Q on kb=0) visible
        if (kb + 1 < nkb) {
            const int kn = k0 + 64;
            const uint32_t bq = (uint32_t)((kb + 1) & 1) * ATILE;
#pragma unroll
            for (int it = 0; it < 2; it++) {
                const int rr = trow + it * 32;
                const size_t src = (size_t)(kn + rr) * HD + tcol;
                const uint32_t dst = bq + tdst + (uint32_t)(it * 32 * ARPB);
                cp_async16(bKh + dst, Kh + src);
                cp_async16(bKl + dst, Kl + src);
                cp_async16(bVh + dst, Vh + src);
                cp_async16(bVl + dst, Vl + src);
            }
            cp_commit();
        }

        // S = Q @ K^T (3-product), RAW distance 2
        float s[8][4];
#pragma unroll
        for (int j = 0; j < 8; j++)
#pragma unroll
            for (int t = 0; t < 4; t++) s[j][t] = 0.0f;
#pragma unroll
        for (int ds = 0; ds < 4; ds++) {
            uint32_t fqh[4], fql[4];
            ldm_x4(fqh, bQh + qa_off + ds * 32);
            ldm_x4(fql, bQl + qa_off + ds * 32);
#pragma unroll
            for (int jp = 0; jp < 4; jp++) {
                uint32_t fkh[4], fkl[4];
                ldm_x4(fkh, bKh + bo + kb4_off[jp] + ds * 32);
                ldm_x4(fkl, bKl + bo + kb4_off[jp] + ds * 32);
                mma_bf16(s[2*jp],   fqh, fkh + 0);
                mma_bf16(s[2*jp+1], fqh, fkh + 2);
                mma_bf16(s[2*jp],   fqh, fkl + 0);
                mma_bf16(s[2*jp+1], fqh, fkl + 2);
                mma_bf16(s[2*jp],   fql, fkh + 0);
                mma_bf16(s[2*jp+1], fql, fkh + 2);
            }
        }

        // mask + online softmax (rows qr0, qr1)
        float rmax0 = -3.0e38f, rmax1 = -3.0e38f;
#pragma unroll
        for (int j = 0; j < 8; j++) {
            const int k = k0 + j*8 + c2;
            const float2 amv = *(const float2*)(am + k);
            s[j][0] = (k   <= qr0) ? s[j][0]*0.125f + amv.x : -10000.0f + amv.x;
            s[j][1] = (k+1 <= qr0) ? s[j][1]*0.125f + amv.y : -10000.0f + amv.y;
            s[j][2] = (k   <= qr1) ? s[j][2]*0.125f + amv.x : -10000.0f + amv.x;
            s[j][3] = (k+1 <= qr1) ? s[j][3]*0.125f + amv.y : -10000.0f + amv.y;
            rmax0 = fmaxf(rmax0, fmaxf(s[j][0], s[j][1]));
            rmax1 = fmaxf(rmax1, fmaxf(s[j][2], s[j][3]));
        }
        rmax0 = fmaxf(rmax0, __shfl_xor_sync(0xffffffffu, rmax0, 1));
        rmax0 = fmaxf(rmax0, __shfl_xor_sync(0xffffffffu, rmax0, 2));
        rmax1 = fmaxf(rmax1, __shfl_xor_sync(0xffffffffu, rmax1, 1));
        rmax1 = fmaxf(rmax1, __shfl_xor_sync(0xffffffffu, rmax1, 2));
        const float mnew0 = fmaxf(mrow0, rmax0);
        const float mnew1 = fmaxf(mrow1, rmax1);
        const float corr0 = __expf(mrow0 - mnew0);
        const float corr1 = __expf(mrow1 - mnew1);
        float rsum0 = 0.0f, rsum1 = 0.0f;
#pragma unroll
        for (int j = 0; j < 8; j++) {
            s[j][0] = __expf(s[j][0] - mnew0);
            s[j][1] = __expf(s[j][1] - mnew0);
            s[j][2] = __expf(s[j][2] - mnew1);
            s[j][3] = __expf(s[j][3] - mnew1);
            rsum0 += s[j][0] + s[j][1];
            rsum1 += s[j][2] + s[j][3];
        }
        rsum0 += __shfl_xor_sync(0xffffffffu, rsum0, 1);
        rsum0 += __shfl_xor_sync(0xffffffffu, rsum0, 2);
        rsum1 += __shfl_xor_sync(0xffffffffu, rsum1, 1);
        rsum1 += __shfl_xor_sync(0xffffffffu, rsum1, 2);
        lrow0 = lrow0 * corr0 + rsum0;
        lrow1 = lrow1 * corr1 + rsum1;
        mrow0 = mnew0; mrow1 = mnew1;
#pragma unroll
        for (int j = 0; j < 8; j++) {
            acc[j][0] *= corr0; acc[j][1] *= corr0;
            acc[j][2] *= corr1; acc[j][3] *= corr1;
        }

        // P fragments (register repack: A-frag t from S n-frags 2t, 2t+1)
        uint32_t fph[4][4], fpl[4][4];
#pragma unroll
        for (int t = 0; t < 4; t++) {
            split2(s[2*t][0],   s[2*t][1],   fph[t][0], fpl[t][0]);
            split2(s[2*t][2],   s[2*t][3],   fph[t][1], fpl[t][1]);
            split2(s[2*t+1][0], s[2*t+1][1], fph[t][2], fpl[t][2]);
            split2(s[2*t+1][2], s[2*t+1][3], fph[t][3], fpl[t][3]);
        }

        // O += P @ V (3-product; V x4.trans), RAW distance 2
#pragma unroll
        for (int t = 0; t < 4; t++) {
            const uint32_t ro = bo + vt4 + (uint32_t)(t * 16 * ARPB);
#pragma unroll
            for (int dnp = 0; dnp < 4; dnp++) {
                uint32_t fvh[4], fvl[4];
                ldm_x4t(fvh, bVh + ro + dnp * 32);
                ldm_x4t(fvl, bVl + ro + dnp * 32);
                mma_bf16(acc[2*dnp],   fph[t], fvh + 0);
                mma_bf16(acc[2*dnp+1], fph[t], fvh + 2);
                mma_bf16(acc[2*dnp],   fph[t], fvl + 0);
                mma_bf16(acc[2*dnp+1], fph[t], fvl + 2);
                mma_bf16(acc[2*dnp],   fpl[t], fvh + 0);
                mma_bf16(acc[2*dnp+1], fpl[t], fvh + 2);
            }
        }
    }

    // epilogue: normalize, bf16 hi/lo split into g_Ah/g_Al at [b, q_view, h*64+d]
    const float inv0 = 1.0f / lrow0;
    const float inv1 = 1.0f / lrow1;
#pragma unroll
    for (int dn = 0; dn < 8; dn++) {
        const int d = dn*8 + c2;
        uint32_t hi0, lo0, hi1, lo1;
        split2(acc[dn][0]*inv0, acc[dn][1]*inv0, hi0, lo0);
        split2(acc[dn][2]*inv1, acc[dn][3]*inv1, hi1, lo1);
        const size_t i0 = ((size_t)b * SEQ + qr0) * NX + h * HD + d;
        const size_t i1 = ((size_t)b * SEQ + qr1) * NX + h * HD + d;
        *(uint32_t*)(g_Ah + i0) = hi0;
        *(uint32_t*)(g_Al + i0) = lo0;
        *(uint32_t*)(g_Ah + i1) = hi1;
        *(uint32_t*)(g_Al + i1) = lo1;
    }
}

// ---------------------------------------------------------------------------
extern "C" void kernel_launch(void* const* d_in, const int* in_sizes, int n_in,
                              void* d_out, int out_size)
{
    const float* hidden = (const float*)d_in[0];
    const float* amask  = (const float*)d_in[1];
    const float* w_attn = (const float*)d_in[2];
    const float* b_attn = (const float*)d_in[3];
    const float* w_proj = (const float*)d_in[4];
    const float* b_proj = (const float*)d_in[5];
    float* out = (float*)d_out;

    // Host-side attribute set: not a stream op, graph-capture-safe, idempotent.
    cudaFuncSetAttribute(attn_mma, cudaFuncAttributeMaxDynamicSharedMemorySize,
                         ATTN_SMEM);

    __nv_bfloat16 *Bh1, *Bl1, *Bh2, *Bl2, *Ah, *Al;
    cudaGetSymbolAddress((void**)&Bh1, g_Bh1);
    cudaGetSymbolAddress((void**)&Bl1, g_Bl1);
    cudaGetSymbolAddress((void**)&Bh2, g_Bh2);
    cudaGetSymbolAddress((void**)&Bl2, g_Bl2);
    cudaGetSymbolAddress((void**)&Ah,  g_Ah);
    cudaGetSymbolAddress((void**)&Al,  g_Al);

    // Pre-pass: transpose+split weights, split activations
    wsplitT<<<dim3(NQKV/32, NX/32), 256>>>(w_attn, Bh1, Bl1, NX, NQKV);
    wsplitT<<<dim3(NX/32,   NX/32), 256>>>(w_proj, Bh2, Bl2, NX, NX);
    asplit<<<(MROWS*NX)/(256*4), 256>>>(hidden, Ah, Al);

    // 1) QKV = X @ W_attn + b -> bf16 hi/lo Q/K/V, quirky per-head layout
    mma_gemm_impl<<<dim3(NQKV/128, MROWS/128), 256>>>(
        Ah, Al, Bh1, Bl1, b_attn, nullptr, NQKV, NX, 1);

    // 2) HMMA flash attention -> bf16 hi/lo activations
    attn_mma<<<dim3(SEQ/128, NH, BSZ), 256, ATTN_SMEM>>>(amask);

    // 3) out = A @ W_proj + b
    mma_gemm_impl<<<dim3(NX/128, MROWS/128), 256>>>(
        Ah, Al, Bh2, Bl2, b_proj, out, NX, NX, 0);
}